// round 1
// baseline (speedup 1.0000x reference)
#include <cuda_runtime.h>

#define B_  2
#define S_  2048
#define D_  1024
#define H_  16
#define HD_ 64
#define M_  (B_*S_)   // 4096

// Scratch (allocation-free rule: static device globals)
__device__ float g_q[B_*H_*S_*HD_];   // [B,H,S,HD]
__device__ float g_k[B_*H_*S_*HD_];
__device__ float g_v[B_*H_*S_*HD_];
__device__ float g_o[M_*D_];          // [B,S,D] attention output (heads merged)

// ---------------------------------------------------------------------------
// 128x128x8 tiled SGEMM: C = A[M,K] * W[K,N] + bias, epilogue scatters into
// [B,H,S,HD] layout. grid.z selects (Wq,bq)->g_q, (Wk,bk)->g_k, (Wv,bv)->g_v.
// ---------------------------------------------------------------------------
__global__ void __launch_bounds__(256) qkv_gemm(
    const float* __restrict__ x,
    const float* __restrict__ Wq, const float* __restrict__ bq,
    const float* __restrict__ Wk, const float* __restrict__ bk,
    const float* __restrict__ Wv, const float* __restrict__ bv)
{
    const float* W; const float* bias; float* Out;
    if (blockIdx.z == 0)      { W = Wq; bias = bq; Out = g_q; }
    else if (blockIdx.z == 1) { W = Wk; bias = bk; Out = g_k; }
    else                      { W = Wv; bias = bv; Out = g_v; }

    __shared__ float As[8][128];   // [k][m]
    __shared__ float Bs[8][128];   // [k][n]

    const int tid = threadIdx.x;
    const int m0 = blockIdx.y * 128;
    const int n0 = blockIdx.x * 128;
    const int tx = tid & 15;       // 16 col groups of 8
    const int ty = tid >> 4;       // 16 row groups of 8

    float acc[8][8] = {};

    const int arow = tid >> 1;          // 0..127
    const int acol = (tid & 1) * 4;     // 0 or 4
    const int brow = tid >> 5;          // 0..7
    const int bcol = (tid & 31) * 4;    // 0..124

    const float* Aptr = x + (m0 + arow) * D_ + acol;
    const float* Wptr = W + brow * D_ + n0 + bcol;

    for (int k0 = 0; k0 < D_; k0 += 8) {
        float4 av = *(const float4*)(Aptr + k0);
        As[acol+0][arow] = av.x;
        As[acol+1][arow] = av.y;
        As[acol+2][arow] = av.z;
        As[acol+3][arow] = av.w;
        *(float4*)&Bs[brow][bcol] = *(const float4*)(Wptr + (size_t)k0 * D_);
        __syncthreads();
        #pragma unroll
        for (int kk = 0; kk < 8; ++kk) {
            float4 a0 = *(float4*)&As[kk][ty*8];
            float4 a1 = *(float4*)&As[kk][ty*8+4];
            float4 b0 = *(float4*)&Bs[kk][tx*8];
            float4 b1 = *(float4*)&Bs[kk][tx*8+4];
            float a[8] = {a0.x,a0.y,a0.z,a0.w,a1.x,a1.y,a1.z,a1.w};
            float b[8] = {b0.x,b0.y,b0.z,b0.w,b1.x,b1.y,b1.z,b1.w};
            #pragma unroll
            for (int i = 0; i < 8; ++i)
                #pragma unroll
                for (int j = 0; j < 8; ++j)
                    acc[i][j] += a[i] * b[j];
        }
        __syncthreads();
    }

    // Scatter epilogue: (m,n) -> [b, h, s, hd]
    #pragma unroll
    for (int i = 0; i < 8; ++i) {
        int m = m0 + ty*8 + i;
        int b = m >> 11;          // m / 2048
        int s = m & 2047;
        #pragma unroll
        for (int j = 0; j < 8; ++j) {
            int n  = n0 + tx*8 + j;
            int h  = n >> 6;
            int hd = n & 63;
            Out[(((b*H_ + h)*S_) + s)*HD_ + hd] = acc[i][j] + bias[n];
        }
    }
}

// ---------------------------------------------------------------------------
// Output projection: d_out = g_o[M,D] * Wo + bo (contiguous epilogue)
// ---------------------------------------------------------------------------
__global__ void __launch_bounds__(256) out_gemm(
    const float* __restrict__ Wo, const float* __restrict__ bo,
    float* __restrict__ out)
{
    __shared__ float As[8][128];
    __shared__ float Bs[8][128];

    const int tid = threadIdx.x;
    const int m0 = blockIdx.y * 128;
    const int n0 = blockIdx.x * 128;
    const int tx = tid & 15;
    const int ty = tid >> 4;

    float acc[8][8] = {};

    const int arow = tid >> 1;
    const int acol = (tid & 1) * 4;
    const int brow = tid >> 5;
    const int bcol = (tid & 31) * 4;

    const float* Aptr = g_o + (size_t)(m0 + arow) * D_ + acol;
    const float* Wptr = Wo + (size_t)brow * D_ + n0 + bcol;

    for (int k0 = 0; k0 < D_; k0 += 8) {
        float4 av = *(const float4*)(Aptr + k0);
        As[acol+0][arow] = av.x;
        As[acol+1][arow] = av.y;
        As[acol+2][arow] = av.z;
        As[acol+3][arow] = av.w;
        *(float4*)&Bs[brow][bcol] = *(const float4*)(Wptr + (size_t)k0 * D_);
        __syncthreads();
        #pragma unroll
        for (int kk = 0; kk < 8; ++kk) {
            float4 a0 = *(float4*)&As[kk][ty*8];
            float4 a1 = *(float4*)&As[kk][ty*8+4];
            float4 b0 = *(float4*)&Bs[kk][tx*8];
            float4 b1 = *(float4*)&Bs[kk][tx*8+4];
            float a[8] = {a0.x,a0.y,a0.z,a0.w,a1.x,a1.y,a1.z,a1.w};
            float b[8] = {b0.x,b0.y,b0.z,b0.w,b1.x,b1.y,b1.z,b1.w};
            #pragma unroll
            for (int i = 0; i < 8; ++i)
                #pragma unroll
                for (int j = 0; j < 8; ++j)
                    acc[i][j] += a[i] * b[j];
        }
        __syncthreads();
    }

    #pragma unroll
    for (int i = 0; i < 8; ++i) {
        int m = m0 + ty*8 + i;
        #pragma unroll
        for (int jj = 0; jj < 8; jj += 4) {
            int n = n0 + tx*8 + jj;
            float4 v;
            v.x = acc[i][jj+0] + bo[n+0];
            v.y = acc[i][jj+1] + bo[n+1];
            v.z = acc[i][jj+2] + bo[n+2];
            v.w = acc[i][jj+3] + bo[n+3];
            *(float4*)&out[(size_t)m * D_ + n] = v;
        }
    }
}

// ---------------------------------------------------------------------------
// Flash attention (fp32), causal. Block = (q-tile of 64 rows, h, b).
// 256 threads: 4 threads per q-row, each owns a 16-wide slice of HD=64.
// ---------------------------------------------------------------------------
__global__ void __launch_bounds__(256) attn_kernel()
{
    const int qt = blockIdx.x;     // 0..31
    const int h  = blockIdx.y;
    const int b  = blockIdx.z;
    const int q0 = qt * 64;

    const float* Qb = g_q + (size_t)((b*H_ + h) * S_) * HD_;
    const float* Kb = g_k + (size_t)((b*H_ + h) * S_) * HD_;
    const float* Vb = g_v + (size_t)((b*H_ + h) * S_) * HD_;

    __shared__ float Ks[64][64];
    __shared__ float Vs[64][64];
    float* ksbase = &Ks[0][0];
    float* vsbase = &Vs[0][0];

    const int tid = threadIdx.x;
    const int r = tid >> 2;        // q row within tile: 0..63
    const int g = tid & 3;         // d-slice: cols [g*16, g*16+16)

    // q fragment (16 floats of this thread's d-slice)
    float qf[16];
    #pragma unroll
    for (int i = 0; i < 16; i += 4) {
        float4 v = *(const float4*)&Qb[(size_t)(q0 + r) * HD_ + g*16 + i];
        qf[i+0] = v.x; qf[i+1] = v.y; qf[i+2] = v.z; qf[i+3] = v.w;
    }

    float of[16];
    #pragma unroll
    for (int i = 0; i < 16; ++i) of[i] = 0.f;
    float m = -1e30f;
    float l = 0.f;
    const float scale = 0.125f;    // 1/sqrt(64)

    const int nkt = qt + 1;        // causal: only tiles up to the diagonal
    for (int kt = 0; kt < nkt; ++kt) {
        const int k0 = kt * 64;
        // stage K, V tiles (64x64 each)
        for (int idx = tid * 4; idx < 64*64; idx += 256*4) {
            *(float4*)(ksbase + idx) = *(const float4*)&Kb[(size_t)k0 * HD_ + idx];
            *(float4*)(vsbase + idx) = *(const float4*)&Vb[(size_t)k0 * HD_ + idx];
        }
        __syncthreads();

        // partial scores over this thread's d-slice
        float s[64];
        #pragma unroll
        for (int j = 0; j < 64; ++j) {
            float acc = 0.f;
            #pragma unroll
            for (int i = 0; i < 16; i += 4) {
                float4 kv = *(const float4*)&Ks[j][g*16 + i];
                acc += qf[i+0]*kv.x + qf[i+1]*kv.y + qf[i+2]*kv.z + qf[i+3]*kv.w;
            }
            s[j] = acc;
        }
        // reduce across the 4-thread group (lanes 4r..4r+3, same warp)
        const bool diag = (kt == qt);
        #pragma unroll
        for (int j = 0; j < 64; ++j) {
            float v = s[j];
            v += __shfl_xor_sync(0xffffffffu, v, 1);
            v += __shfl_xor_sync(0xffffffffu, v, 2);
            v *= scale;
            if (diag && (k0 + j > q0 + r)) v = -1e30f;
            s[j] = v;
        }
        // online softmax
        float mt = m;
        #pragma unroll
        for (int j = 0; j < 64; ++j) mt = fmaxf(mt, s[j]);
        float alpha = __expf(m - mt);
        l *= alpha;
        #pragma unroll
        for (int i = 0; i < 16; ++i) of[i] *= alpha;
        #pragma unroll
        for (int j = 0; j < 64; ++j) {
            float p = __expf(s[j] - mt);
            l += p;
            #pragma unroll
            for (int i = 0; i < 16; i += 4) {
                float4 vv = *(const float4*)&Vs[j][g*16 + i];
                of[i+0] += p * vv.x;
                of[i+1] += p * vv.y;
                of[i+2] += p * vv.z;
                of[i+3] += p * vv.w;
            }
        }
        m = mt;
        __syncthreads();
    }

    const float inv = 1.f / l;
    float* obase = g_o + (size_t)(b*S_ + q0 + r) * D_ + h*HD_ + g*16;
    #pragma unroll
    for (int i = 0; i < 16; i += 4) {
        float4 v;
        v.x = of[i+0] * inv;
        v.y = of[i+1] * inv;
        v.z = of[i+2] * inv;
        v.w = of[i+3] * inv;
        *(float4*)(obase + i) = v;
    }
}

// ---------------------------------------------------------------------------
extern "C" void kernel_launch(void* const* d_in, const int* in_sizes, int n_in,
                              void* d_out, int out_size)
{
    (void)in_sizes; (void)n_in; (void)out_size;
    const float* x  = (const float*)d_in[0];
    const float* Wq = (const float*)d_in[1];
    const float* bq = (const float*)d_in[2];
    const float* Wk = (const float*)d_in[3];
    const float* bk = (const float*)d_in[4];
    const float* Wv = (const float*)d_in[5];
    const float* bv = (const float*)d_in[6];
    const float* Wo = (const float*)d_in[7];
    const float* bo = (const float*)d_in[8];
    float* out = (float*)d_out;

    dim3 gq(D_/128, M_/128, 3);     // 8 x 32 x 3
    qkv_gemm<<<gq, 256>>>(x, Wq, bq, Wk, bk, Wv, bv);

    dim3 ga(S_/64, H_, B_);         // 32 x 16 x 2
    attn_kernel<<<ga, 256>>>();

    dim3 go(D_/128, M_/128, 1);     // 8 x 32
    out_gemm<<<go, 256>>>(Wo, bo, out);
}

// round 2
// speedup vs baseline: 1.8961x; 1.8961x over previous
#include <cuda_runtime.h>

#define B_  2
#define S_  2048
#define D_  1024
#define H_  16
#define HD_ 64
#define M_  (B_*S_)   // 4096
#define BK_ 16

// Scratch (allocation-free rule: static device globals)
__device__ float g_q[B_*H_*S_*HD_];   // [B,H,S,HD]
__device__ float g_k[B_*H_*S_*HD_];
__device__ float g_v[B_*H_*S_*HD_];
__device__ float g_o[M_*D_];          // [B,S,D] attention output (heads merged)

// ---------------------------------------------------------------------------
// 128x128x16 double-buffered SGEMM: C = A[M,K] * W[K,N] + bias.
// Epilogue scatters into [B,H,S,HD]. grid.z selects Q/K/V.
// ---------------------------------------------------------------------------
__global__ void __launch_bounds__(256) qkv_gemm(
    const float* __restrict__ x,
    const float* __restrict__ Wq, const float* __restrict__ bq,
    const float* __restrict__ Wk, const float* __restrict__ bk,
    const float* __restrict__ Wv, const float* __restrict__ bv)
{
    const float* W; const float* bias; float* Out;
    if (blockIdx.z == 0)      { W = Wq; bias = bq; Out = g_q; }
    else if (blockIdx.z == 1) { W = Wk; bias = bk; Out = g_k; }
    else                      { W = Wv; bias = bv; Out = g_v; }

    __shared__ float As[2][BK_][128];   // [k][m]
    __shared__ float Bs[2][BK_][128];   // [k][n]

    const int tid = threadIdx.x;
    const int m0 = blockIdx.y * 128;
    const int n0 = blockIdx.x * 128;
    const int tx = tid & 15;
    const int ty = tid >> 4;

    const int arow = tid >> 1;          // 0..127
    const int acol = (tid & 1) * 8;     // 0 or 8
    const int brow = tid >> 4;          // 0..15
    const int bcol = (tid & 15) * 8;    // 0..120

    const float* Ap = x + (size_t)(m0 + arow) * D_ + acol;
    const float* Wp = W + (size_t)brow * D_ + n0 + bcol;

    float4 a0 = *(const float4*)(Ap);
    float4 a1 = *(const float4*)(Ap + 4);
    float4 b0 = *(const float4*)(Wp);
    float4 b1 = *(const float4*)(Wp + 4);

    As[0][acol+0][arow] = a0.x; As[0][acol+1][arow] = a0.y;
    As[0][acol+2][arow] = a0.z; As[0][acol+3][arow] = a0.w;
    As[0][acol+4][arow] = a1.x; As[0][acol+5][arow] = a1.y;
    As[0][acol+6][arow] = a1.z; As[0][acol+7][arow] = a1.w;
    *(float4*)&Bs[0][brow][bcol]   = b0;
    *(float4*)&Bs[0][brow][bcol+4] = b1;
    __syncthreads();

    float acc[8][8] = {};
    const int NT = D_ / BK_;

    for (int t = 0; t < NT; ++t) {
        const int db = t & 1;
        if (t + 1 < NT) {
            const int k0 = (t + 1) * BK_;
            a0 = *(const float4*)(Ap + k0);
            a1 = *(const float4*)(Ap + k0 + 4);
            b0 = *(const float4*)(Wp + (size_t)k0 * D_);
            b1 = *(const float4*)(Wp + (size_t)k0 * D_ + 4);
        }
        #pragma unroll
        for (int kk = 0; kk < BK_; ++kk) {
            float4 xa0 = *(float4*)&As[db][kk][ty*8];
            float4 xa1 = *(float4*)&As[db][kk][ty*8+4];
            float4 xb0 = *(float4*)&Bs[db][kk][tx*8];
            float4 xb1 = *(float4*)&Bs[db][kk][tx*8+4];
            float a[8] = {xa0.x,xa0.y,xa0.z,xa0.w,xa1.x,xa1.y,xa1.z,xa1.w};
            float b[8] = {xb0.x,xb0.y,xb0.z,xb0.w,xb1.x,xb1.y,xb1.z,xb1.w};
            #pragma unroll
            for (int i = 0; i < 8; ++i)
                #pragma unroll
                for (int j = 0; j < 8; ++j)
                    acc[i][j] += a[i] * b[j];
        }
        if (t + 1 < NT) {
            const int nb = db ^ 1;
            As[nb][acol+0][arow] = a0.x; As[nb][acol+1][arow] = a0.y;
            As[nb][acol+2][arow] = a0.z; As[nb][acol+3][arow] = a0.w;
            As[nb][acol+4][arow] = a1.x; As[nb][acol+5][arow] = a1.y;
            As[nb][acol+6][arow] = a1.z; As[nb][acol+7][arow] = a1.w;
            *(float4*)&Bs[nb][brow][bcol]   = b0;
            *(float4*)&Bs[nb][brow][bcol+4] = b1;
        }
        __syncthreads();
    }

    // Scatter epilogue: (m,n) -> [b, h, s, hd]
    #pragma unroll
    for (int i = 0; i < 8; ++i) {
        int m = m0 + ty*8 + i;
        int b = m >> 11;
        int s = m & 2047;
        #pragma unroll
        for (int j = 0; j < 8; ++j) {
            int n  = n0 + tx*8 + j;
            int h  = n >> 6;
            int hd = n & 63;
            Out[(((size_t)(b*H_ + h)*S_) + s)*HD_ + hd] = acc[i][j] + bias[n];
        }
    }
}

// ---------------------------------------------------------------------------
// Output projection: d_out = g_o[M,D] * Wo + bo
// ---------------------------------------------------------------------------
__global__ void __launch_bounds__(256) out_gemm(
    const float* __restrict__ Wo, const float* __restrict__ bo,
    float* __restrict__ out)
{
    __shared__ float As[2][BK_][128];
    __shared__ float Bs[2][BK_][128];

    const int tid = threadIdx.x;
    const int m0 = blockIdx.y * 128;
    const int n0 = blockIdx.x * 128;
    const int tx = tid & 15;
    const int ty = tid >> 4;

    const int arow = tid >> 1;
    const int acol = (tid & 1) * 8;
    const int brow = tid >> 4;
    const int bcol = (tid & 15) * 8;

    const float* Ap = g_o + (size_t)(m0 + arow) * D_ + acol;
    const float* Wp = Wo + (size_t)brow * D_ + n0 + bcol;

    float4 a0 = *(const float4*)(Ap);
    float4 a1 = *(const float4*)(Ap + 4);
    float4 b0 = *(const float4*)(Wp);
    float4 b1 = *(const float4*)(Wp + 4);

    As[0][acol+0][arow] = a0.x; As[0][acol+1][arow] = a0.y;
    As[0][acol+2][arow] = a0.z; As[0][acol+3][arow] = a0.w;
    As[0][acol+4][arow] = a1.x; As[0][acol+5][arow] = a1.y;
    As[0][acol+6][arow] = a1.z; As[0][acol+7][arow] = a1.w;
    *(float4*)&Bs[0][brow][bcol]   = b0;
    *(float4*)&Bs[0][brow][bcol+4] = b1;
    __syncthreads();

    float acc[8][8] = {};
    const int NT = D_ / BK_;

    for (int t = 0; t < NT; ++t) {
        const int db = t & 1;
        if (t + 1 < NT) {
            const int k0 = (t + 1) * BK_;
            a0 = *(const float4*)(Ap + k0);
            a1 = *(const float4*)(Ap + k0 + 4);
            b0 = *(const float4*)(Wp + (size_t)k0 * D_);
            b1 = *(const float4*)(Wp + (size_t)k0 * D_ + 4);
        }
        #pragma unroll
        for (int kk = 0; kk < BK_; ++kk) {
            float4 xa0 = *(float4*)&As[db][kk][ty*8];
            float4 xa1 = *(float4*)&As[db][kk][ty*8+4];
            float4 xb0 = *(float4*)&Bs[db][kk][tx*8];
            float4 xb1 = *(float4*)&Bs[db][kk][tx*8+4];
            float a[8] = {xa0.x,xa0.y,xa0.z,xa0.w,xa1.x,xa1.y,xa1.z,xa1.w};
            float b[8] = {xb0.x,xb0.y,xb0.z,xb0.w,xb1.x,xb1.y,xb1.z,xb1.w};
            #pragma unroll
            for (int i = 0; i < 8; ++i)
                #pragma unroll
                for (int j = 0; j < 8; ++j)
                    acc[i][j] += a[i] * b[j];
        }
        if (t + 1 < NT) {
            const int nb = db ^ 1;
            As[nb][acol+0][arow] = a0.x; As[nb][acol+1][arow] = a0.y;
            As[nb][acol+2][arow] = a0.z; As[nb][acol+3][arow] = a0.w;
            As[nb][acol+4][arow] = a1.x; As[nb][acol+5][arow] = a1.y;
            As[nb][acol+6][arow] = a1.z; As[nb][acol+7][arow] = a1.w;
            *(float4*)&Bs[nb][brow][bcol]   = b0;
            *(float4*)&Bs[nb][brow][bcol+4] = b1;
        }
        __syncthreads();
    }

    #pragma unroll
    for (int i = 0; i < 8; ++i) {
        int m = m0 + ty*8 + i;
        #pragma unroll
        for (int jj = 0; jj < 8; jj += 4) {
            int n = n0 + tx*8 + jj;
            float4 v;
            v.x = acc[i][jj+0] + bo[n+0];
            v.y = acc[i][jj+1] + bo[n+1];
            v.z = acc[i][jj+2] + bo[n+2];
            v.w = acc[i][jj+3] + bo[n+3];
            *(float4*)&out[(size_t)m * D_ + n] = v;
        }
    }
}

// ---------------------------------------------------------------------------
// Flash attention v2 (fp32), causal. Register-tiled GEMM structure.
// Block = 64 q-rows of one (b,h); 256 threads as 16x16 grid.
// Thread (ty,tx): S rows 4ty..4ty+3 x cols 2tx..2tx+1; O rows 4ty+i x cols 4tx+j.
// K-tile = 32 rows.
// ---------------------------------------------------------------------------
__global__ void __launch_bounds__(256) attn_kernel()
{
    const int qt = blockIdx.x;     // 0..31
    const int h  = blockIdx.y;
    const int b  = blockIdx.z;
    const int q0 = qt * 64;

    const float* Qb = g_q + (size_t)(b*H_ + h) * S_ * HD_;
    const float* Kb = g_k + (size_t)(b*H_ + h) * S_ * HD_;
    const float* Vb = g_v + (size_t)(b*H_ + h) * S_ * HD_;

    __shared__ float Qt[64][68];   // [d][qrow]  (transposed)
    __shared__ float Kt[64][34];   // [d][krow]  (transposed)
    __shared__ float Vs[32][64];   // [krow][d]  (natural)
    __shared__ float Pt[32][65];   // [krow][qrow] (transposed P)

    const int tid = threadIdx.x;
    const int tx = tid & 15;
    const int ty = tid >> 4;

    // Stage Q transposed (once)
    {
        const int i = tid >> 2;          // q row 0..63
        const int c = tid & 3;           // d chunk of 16
        const float* qrow = Qb + (size_t)(q0 + i) * HD_ + c*16;
        #pragma unroll
        for (int u = 0; u < 4; ++u) {
            float4 v = *(const float4*)(qrow + 4*u);
            Qt[c*16 + 4*u + 0][i] = v.x;
            Qt[c*16 + 4*u + 1][i] = v.y;
            Qt[c*16 + 4*u + 2][i] = v.z;
            Qt[c*16 + 4*u + 3][i] = v.w;
        }
    }

    float o[4][4];
    #pragma unroll
    for (int i = 0; i < 4; ++i)
        #pragma unroll
        for (int j = 0; j < 4; ++j) o[i][j] = 0.f;
    float m[4] = {-1e30f, -1e30f, -1e30f, -1e30f};
    float l[4] = {0.f, 0.f, 0.f, 0.f};

    const int stgj = tid >> 3;     // 0..31 (staging row)
    const int stgc = tid & 7;      // 0..7  (d chunk of 8)

    const int nkt = 2 * (qt + 1);
    for (int kt = 0; kt < nkt; ++kt) {
        const int k0 = kt * 32;
        __syncthreads();   // Kt/Vs/Pt free

        // Stage K (transposed) and V (natural)
        {
            const float* krow = Kb + (size_t)(k0 + stgj) * HD_ + stgc*8;
            #pragma unroll
            for (int u = 0; u < 2; ++u) {
                float4 v = *(const float4*)(krow + 4*u);
                Kt[stgc*8 + 4*u + 0][stgj] = v.x;
                Kt[stgc*8 + 4*u + 1][stgj] = v.y;
                Kt[stgc*8 + 4*u + 2][stgj] = v.z;
                Kt[stgc*8 + 4*u + 3][stgj] = v.w;
            }
            const float* vrow = Vb + (size_t)(k0 + stgj) * HD_ + stgc*8;
            #pragma unroll
            for (int u = 0; u < 2; ++u)
                *(float4*)&Vs[stgj][stgc*8 + 4*u] = *(const float4*)(vrow + 4*u);
        }
        __syncthreads();

        // S = Q @ K^T : 64x32 tile, outer product over d
        float s[4][2] = {};
        #pragma unroll
        for (int d = 0; d < 64; ++d) {
            float4 qa = *(float4*)&Qt[d][ty*4];
            float2 kb = *(float2*)&Kt[d][tx*2];
            s[0][0] += qa.x*kb.x; s[0][1] += qa.x*kb.y;
            s[1][0] += qa.y*kb.x; s[1][1] += qa.y*kb.y;
            s[2][0] += qa.z*kb.x; s[2][1] += qa.z*kb.y;
            s[3][0] += qa.w*kb.x; s[3][1] += qa.w*kb.y;
        }

        // Online softmax (rows 4ty+i; reduce over tx via half-warp shfl)
        const bool needmask = (k0 + 31 > q0);
        #pragma unroll
        for (int i = 0; i < 4; ++i) {
            float s0 = s[i][0] * 0.125f;
            float s1 = s[i][1] * 0.125f;
            if (needmask) {
                const int row = q0 + ty*4 + i;
                if (k0 + tx*2 + 0 > row) s0 = -1e30f;
                if (k0 + tx*2 + 1 > row) s1 = -1e30f;
            }
            float rm = fmaxf(s0, s1);
            rm = fmaxf(rm, __shfl_xor_sync(0xffffffffu, rm, 1));
            rm = fmaxf(rm, __shfl_xor_sync(0xffffffffu, rm, 2));
            rm = fmaxf(rm, __shfl_xor_sync(0xffffffffu, rm, 4));
            rm = fmaxf(rm, __shfl_xor_sync(0xffffffffu, rm, 8));
            const float nm = fmaxf(m[i], rm);
            const float alpha = __expf(m[i] - nm);
            m[i] = nm;
            const float p0 = __expf(s0 - nm);
            const float p1 = __expf(s1 - nm);
            float rs = p0 + p1;
            rs += __shfl_xor_sync(0xffffffffu, rs, 1);
            rs += __shfl_xor_sync(0xffffffffu, rs, 2);
            rs += __shfl_xor_sync(0xffffffffu, rs, 4);
            rs += __shfl_xor_sync(0xffffffffu, rs, 8);
            l[i] = l[i] * alpha + rs;
            o[i][0] *= alpha; o[i][1] *= alpha;
            o[i][2] *= alpha; o[i][3] *= alpha;
            Pt[tx*2 + 0][ty*4 + i] = p0;
            Pt[tx*2 + 1][ty*4 + i] = p1;
        }
        __syncthreads();   // Pt ready

        // O += P @ V : rows 4ty+i, cols 4tx+j
        #pragma unroll
        for (int j = 0; j < 32; ++j) {
            float4 vb = *(float4*)&Vs[j][tx*4];
            float pa0 = Pt[j][ty*4 + 0];
            float pa1 = Pt[j][ty*4 + 1];
            float pa2 = Pt[j][ty*4 + 2];
            float pa3 = Pt[j][ty*4 + 3];
            o[0][0] += pa0*vb.x; o[0][1] += pa0*vb.y; o[0][2] += pa0*vb.z; o[0][3] += pa0*vb.w;
            o[1][0] += pa1*vb.x; o[1][1] += pa1*vb.y; o[1][2] += pa1*vb.z; o[1][3] += pa1*vb.w;
            o[2][0] += pa2*vb.x; o[2][1] += pa2*vb.y; o[2][2] += pa2*vb.z; o[2][3] += pa2*vb.w;
            o[3][0] += pa3*vb.x; o[3][1] += pa3*vb.y; o[3][2] += pa3*vb.z; o[3][3] += pa3*vb.w;
        }
    }

    // Normalize and write merged output [B,S,D]
    #pragma unroll
    for (int i = 0; i < 4; ++i) {
        const float inv = 1.f / l[i];
        float4 v;
        v.x = o[i][0] * inv;
        v.y = o[i][1] * inv;
        v.z = o[i][2] * inv;
        v.w = o[i][3] * inv;
        *(float4*)&g_o[(size_t)(b*S_ + q0 + ty*4 + i) * D_ + h*HD_ + tx*4] = v;
    }
}

// ---------------------------------------------------------------------------
extern "C" void kernel_launch(void* const* d_in, const int* in_sizes, int n_in,
                              void* d_out, int out_size)
{
    (void)in_sizes; (void)n_in; (void)out_size;
    const float* x  = (const float*)d_in[0];
    const float* Wq = (const float*)d_in[1];
    const float* bq = (const float*)d_in[2];
    const float* Wk = (const float*)d_in[3];
    const float* bk = (const float*)d_in[4];
    const float* Wv = (const float*)d_in[5];
    const float* bv = (const float*)d_in[6];
    const float* Wo = (const float*)d_in[7];
    const float* bo = (const float*)d_in[8];
    float* out = (float*)d_out;

    dim3 gq(D_/128, M_/128, 3);
    qkv_gemm<<<gq, 256>>>(x, Wq, bq, Wk, bk, Wv, bv);

    dim3 ga(S_/64, H_, B_);
    attn_kernel<<<ga, 256>>>();

    dim3 go(D_/128, M_/128, 1);
    out_gemm<<<go, 256>>>(Wo, bo, out);
}

// round 4
// speedup vs baseline: 2.6482x; 1.3967x over previous
#include <cuda_runtime.h>
#include <cuda_bf16.h>
#include <cstdint>

#define B_  2
#define S_  2048
#define D_  1024
#define H_  16
#define HD_ 64
#define M_  (B_*S_)   // 4096

// ---------------------------------------------------------------------------
// Scratch (allocation-free rule: static device globals)
// ---------------------------------------------------------------------------
__device__ float g_q[M_*D_];   // [B,S,D]
__device__ float g_k[M_*D_];
__device__ float g_v[M_*D_];
__device__ float g_o[M_*D_];   // attention output [B,S,D]

__device__ __nv_bfloat16 g_xhi[M_*D_], g_xlo[M_*D_];   // split x
__device__ __nv_bfloat16 g_ohi[M_*D_], g_olo[M_*D_];   // split g_o
__device__ __nv_bfloat16 g_wthi[4][D_*D_], g_wtlo[4][D_*D_]; // W^T split [N,K]

// ---------------------------------------------------------------------------
__device__ __forceinline__ uint32_t smem_u32(const void* p) {
    uint32_t a;
    asm("{ .reg .u64 t; cvta.to.shared.u64 t, %1; cvt.u32.u64 %0, t; }" : "=r"(a) : "l"(p));
    return a;
}

#define CP_ASYNC16(dst, src) \
    asm volatile("cp.async.cg.shared.global [%0], [%1], 16;" :: "r"(dst), "l"(src))
#define CP_COMMIT()  asm volatile("cp.async.commit_group;" ::: "memory")
#define CP_WAIT(n)   asm volatile("cp.async.wait_group %0;" :: "n"(n) : "memory")

#define LDSM_X4(r0, r1, r2, r3, addr) \
    asm volatile("ldmatrix.sync.aligned.m8n8.x4.shared.b16 {%0,%1,%2,%3}, [%4];" \
        : "=r"(r0), "=r"(r1), "=r"(r2), "=r"(r3) : "r"(addr))

#define MMA_BF16(d, a, b) \
    asm volatile("mma.sync.aligned.m16n8k16.row.col.f32.bf16.bf16.f32 " \
        "{%0,%1,%2,%3}, {%4,%5,%6,%7}, {%8,%9}, {%0,%1,%2,%3};" \
        : "+f"((d)[0]), "+f"((d)[1]), "+f"((d)[2]), "+f"((d)[3]) \
        : "r"((a)[0]), "r"((a)[1]), "r"((a)[2]), "r"((a)[3]), "r"((b)[0]), "r"((b)[1]))

// ---------------------------------------------------------------------------
// Split-convert: fp32 -> (hi, lo) bf16.  sel=0: x (param), sel=1: g_o.
// ---------------------------------------------------------------------------
__global__ void __launch_bounds__(256) convert_split(const float4* __restrict__ xin, int sel)
{
    const int i = blockIdx.x * 256 + threadIdx.x;      // float4 index
    const float4 v = sel ? ((const float4*)g_o)[i] : xin[i];
    __nv_bfloat16* hi = sel ? g_ohi : g_xhi;
    __nv_bfloat16* lo = sel ? g_olo : g_xlo;

    __nv_bfloat16 h0 = __float2bfloat16(v.x), h1 = __float2bfloat16(v.y);
    __nv_bfloat16 h2 = __float2bfloat16(v.z), h3 = __float2bfloat16(v.w);
    __nv_bfloat16 l0 = __float2bfloat16(v.x - __bfloat162float(h0));
    __nv_bfloat16 l1 = __float2bfloat16(v.y - __bfloat162float(h1));
    __nv_bfloat16 l2 = __float2bfloat16(v.z - __bfloat162float(h2));
    __nv_bfloat16 l3 = __float2bfloat16(v.w - __bfloat162float(h3));

    __nv_bfloat162 hp[2] = {{h0, h1}, {h2, h3}};
    __nv_bfloat162 lp[2] = {{l0, l1}, {l2, l3}};
    ((uint2*)hi)[i] = *(uint2*)hp;
    ((uint2*)lo)[i] = *(uint2*)lp;
}

// ---------------------------------------------------------------------------
// Transpose + split: W[K,N] fp32 -> Wt[N,K] (hi,lo) bf16. z selects Wq/Wk/Wv/Wo.
// ---------------------------------------------------------------------------
__global__ void __launch_bounds__(256) transpose_split(
    const float* __restrict__ Wq, const float* __restrict__ Wk,
    const float* __restrict__ Wv, const float* __restrict__ Wo)
{
    const float* W = (blockIdx.z == 0) ? Wq : (blockIdx.z == 1) ? Wk
                   : (blockIdx.z == 2) ? Wv : Wo;
    __nv_bfloat16* Thi = g_wthi[blockIdx.z];
    __nv_bfloat16* Tlo = g_wtlo[blockIdx.z];

    __shared__ float tile[32][33];
    const int tx = threadIdx.x, ty = threadIdx.y;
    const int k0 = blockIdx.x * 32, n0 = blockIdx.y * 32;

    #pragma unroll
    for (int j = 0; j < 32; j += 8)
        tile[ty + j][tx] = W[(size_t)(k0 + ty + j) * D_ + n0 + tx];
    __syncthreads();
    #pragma unroll
    for (int j = 0; j < 32; j += 8) {
        float v = tile[tx][ty + j];
        __nv_bfloat16 h = __float2bfloat16(v);
        __nv_bfloat16 l = __float2bfloat16(v - __bfloat162float(h));
        const size_t idx = (size_t)(n0 + ty + j) * D_ + k0 + tx;
        Thi[idx] = h;
        Tlo[idx] = l;
    }
}

// ---------------------------------------------------------------------------
// Split-bf16 tensor-core GEMM via mma.sync (HMMA):
//   Out[M,1024] = A[M,1024] * Wt^T + bias,  D = Ah*Bh + Ah*Bl + Al*Bh (fp32 acc)
// Tile 128x128, 8 warps (each 64x32), BK=32, cp.async double-buffered.
// ---------------------------------------------------------------------------
#define BK_   32
#define NT_   (D_ / BK_)         // 32 chunks
#define ROWE_ 40                 // padded row: 32 bf16 + 8 pad (80 bytes)
#define TILE_BYTES (128 * ROWE_ * 2)          // 10240
#define STAGE_BYTES (4 * TILE_BYTES)          // 40960 (Ahi,Alo,Bhi,Blo)
#define GSMEM_BYTES (2 * STAGE_BYTES)         // 81920

extern __shared__ char dsm[];

__global__ void __launch_bounds__(256, 2) mma_gemm(int asel, int wsel, int osel,
                                                   const float* __restrict__ bias,
                                                   float* __restrict__ dout)
{
    const __nv_bfloat16* Ahi = asel ? g_ohi : g_xhi;
    const __nv_bfloat16* Alo = asel ? g_olo : g_xlo;
    const __nv_bfloat16* Bhi = g_wthi[wsel];
    const __nv_bfloat16* Blo = g_wtlo[wsel];
    float* Out = (osel == 0) ? g_q : (osel == 1) ? g_k : (osel == 2) ? g_v : dout;

    const int tid  = threadIdx.x;
    const int lane = tid & 31;
    const int wid  = tid >> 5;
    const int wm   = (wid & 1) * 64;     // warp m offset in tile
    const int wn   = (wid >> 1) * 32;    // warp n offset in tile
    const int m0 = blockIdx.y * 128;
    const int n0 = blockIdx.x * 128;

    const uint32_t sb = smem_u32(dsm);

    // cp.async staging: thread handles 2 x 16B per tile per chunk
    const int c0  = tid * 2;             // chunk index 0..511 (x2)
    const int ldr = c0 >> 2;             // row 0..127
    const int ldq = c0 & 3;              // 16B quarter 0..3
    const __nv_bfloat16* srcs[4];
    srcs[0] = Ahi + (size_t)(m0 + ldr) * D_ + ldq * 8;
    srcs[1] = Alo + (size_t)(m0 + ldr) * D_ + ldq * 8;
    srcs[2] = Bhi + (size_t)(n0 + ldr) * D_ + ldq * 8;
    srcs[3] = Blo + (size_t)(n0 + ldr) * D_ + ldq * 8;

    auto issue_stage = [&](int t) {
        const int kc = t * BK_;
        const uint32_t st = sb + (t & 1) * STAGE_BYTES;
        #pragma unroll
        for (int tile = 0; tile < 4; ++tile) {
            uint32_t doff = st + tile * TILE_BYTES + ldr * (ROWE_ * 2) + ldq * 16;
            CP_ASYNC16(doff,      srcs[tile] + kc);
            CP_ASYNC16(doff + 32, srcs[tile] + kc + 16);   // quarter +2 (rows stride 4 quarters)
        }
    };
    // NOTE: each thread covers quarters ldq and ldq+2 of row ldr? No —
    // c0, c0+1 are consecutive quarters. Redo precisely below.

    // --- correct staging: thread t covers 16B chunks (2t) and (2t+1) of each tile
    const int cA = tid * 2, cB = tid * 2 + 1;
    const int rA = cA >> 2, qA = cA & 3;
    const int rB = cB >> 2, qB = cB & 3;

    auto issue = [&](int t) {
        const int kc = t * BK_;
        const uint32_t st = sb + (t & 1) * STAGE_BYTES;
        const __nv_bfloat16* gA[4] = {
            Ahi + (size_t)(m0 + rA) * D_ + kc + qA * 8,
            Alo + (size_t)(m0 + rA) * D_ + kc + qA * 8,
            Bhi + (size_t)(n0 + rA) * D_ + kc + qA * 8,
            Blo + (size_t)(n0 + rA) * D_ + kc + qA * 8 };
        const __nv_bfloat16* gB[4] = {
            Ahi + (size_t)(m0 + rB) * D_ + kc + qB * 8,
            Alo + (size_t)(m0 + rB) * D_ + kc + qB * 8,
            Bhi + (size_t)(n0 + rB) * D_ + kc + qB * 8,
            Blo + (size_t)(n0 + rB) * D_ + kc + qB * 8 };
        #pragma unroll
        for (int tile = 0; tile < 4; ++tile) {
            CP_ASYNC16(st + tile * TILE_BYTES + rA * (ROWE_ * 2) + qA * 16, gA[tile]);
            CP_ASYNC16(st + tile * TILE_BYTES + rB * (ROWE_ * 2) + qB * 16, gB[tile]);
        }
        CP_COMMIT();
    };

    float d[4][4][4];
    #pragma unroll
    for (int i = 0; i < 4; ++i)
        #pragma unroll
        for (int j = 0; j < 4; ++j)
            #pragma unroll
            for (int r = 0; r < 4; ++r) d[i][j][r] = 0.f;

    issue(0);

    // ldmatrix lane addressing (byte offsets inside a tile)
    const int aRow = lane & 15;            // row within 16-row subtile
    const int aK8  = (lane >> 4) * 8;      // k offset 0/8
    const int bRow = (lane & 7) + ((lane >> 4) & 1) * 8;
    const int bK8  = ((lane >> 3) & 1) * 8;

    for (int t = 0; t < NT_; ++t) {
        if (t + 1 < NT_) issue(t + 1);
        if (t + 1 < NT_) { CP_WAIT(1); } else { CP_WAIT(0); }
        __syncthreads();

        const uint32_t st = sb + (t & 1) * STAGE_BYTES;
        // passes: 0 = Ah*Bh, 1 = Ah*Bl, 2 = Al*Bh
        #pragma unroll
        for (int pass = 0; pass < 3; ++pass) {
            const uint32_t At = st + ((pass == 2) ? TILE_BYTES : 0);
            const uint32_t Bt = st + ((pass == 1) ? 3 : 2) * TILE_BYTES;
            #pragma unroll
            for (int ks = 0; ks < BK_; ks += 16) {
                uint32_t bfr[4][2];
                #pragma unroll
                for (int np = 0; np < 2; ++np) {
                    uint32_t addr = Bt + (uint32_t)(wn + np*16 + bRow) * (ROWE_*2)
                                  + (ks + bK8) * 2;
                    uint32_t r0, r1, r2, r3;
                    LDSM_X4(r0, r1, r2, r3, addr);
                    bfr[np*2+0][0] = r0; bfr[np*2+0][1] = r1;
                    bfr[np*2+1][0] = r2; bfr[np*2+1][1] = r3;
                }
                #pragma unroll
                for (int ms = 0; ms < 4; ++ms) {
                    uint32_t a[4];
                    uint32_t addr = At + (uint32_t)(wm + ms*16 + aRow) * (ROWE_*2)
                                  + (ks + aK8) * 2;
                    LDSM_X4(a[0], a[1], a[2], a[3], addr);
                    #pragma unroll
                    for (int ns = 0; ns < 4; ++ns)
                        MMA_BF16(d[ms][ns], a, bfr[ns]);
                }
            }
        }
        __syncthreads();
    }

    // Epilogue: c0,c1 = (row g, col q*2/+1); c2,c3 = (row g+8, same cols)
    const int g = lane >> 2, q = lane & 3;
    #pragma unroll
    for (int ns = 0; ns < 4; ++ns) {
        const int col = n0 + wn + ns * 8 + q * 2;
        const float2 bv = *(const float2*)&bias[col];
        #pragma unroll
        for (int ms = 0; ms < 4; ++ms) {
            const int row = m0 + wm + ms * 16 + g;
            float2 v0 = { d[ms][ns][0] + bv.x, d[ms][ns][1] + bv.y };
            float2 v1 = { d[ms][ns][2] + bv.x, d[ms][ns][3] + bv.y };
            *(float2*)&Out[(size_t)row * D_ + col]       = v0;
            *(float2*)&Out[(size_t)(row + 8) * D_ + col] = v1;
        }
    }
}

// ---------------------------------------------------------------------------
// Flash attention (fp32 FFMA), causal — QKV in [B,S,D] layout.
// ---------------------------------------------------------------------------
__global__ void __launch_bounds__(256) attn_kernel()
{
    const int qt = blockIdx.x;
    const int h  = blockIdx.y;
    const int b  = blockIdx.z;
    const int q0 = qt * 64;
    const size_t hoff = (size_t)h * HD_;

    __shared__ float Qt[64][68];
    __shared__ float Kt[64][34];
    __shared__ float Vs[32][64];
    __shared__ float Pt[32][65];

    const int tid = threadIdx.x;
    const int tx = tid & 15;
    const int ty = tid >> 4;

    {
        const int i = tid >> 2;
        const int c = tid & 3;
        const float* qrow = g_q + (size_t)(b*S_ + q0 + i) * D_ + hoff + c*16;
        #pragma unroll
        for (int u = 0; u < 4; ++u) {
            float4 v = *(const float4*)(qrow + 4*u);
            Qt[c*16 + 4*u + 0][i] = v.x;
            Qt[c*16 + 4*u + 1][i] = v.y;
            Qt[c*16 + 4*u + 2][i] = v.z;
            Qt[c*16 + 4*u + 3][i] = v.w;
        }
    }

    float o[4][4];
    #pragma unroll
    for (int i = 0; i < 4; ++i)
        #pragma unroll
        for (int j = 0; j < 4; ++j) o[i][j] = 0.f;
    float m[4] = {-1e30f, -1e30f, -1e30f, -1e30f};
    float l[4] = {0.f, 0.f, 0.f, 0.f};

    const int stgj = tid >> 3;
    const int stgc = tid & 7;

    const int nkt = 2 * (qt + 1);
    for (int kt = 0; kt < nkt; ++kt) {
        const int k0 = kt * 32;
        __syncthreads();

        {
            const float* krow = g_k + (size_t)(b*S_ + k0 + stgj) * D_ + hoff + stgc*8;
            #pragma unroll
            for (int u = 0; u < 2; ++u) {
                float4 v = *(const float4*)(krow + 4*u);
                Kt[stgc*8 + 4*u + 0][stgj] = v.x;
                Kt[stgc*8 + 4*u + 1][stgj] = v.y;
                Kt[stgc*8 + 4*u + 2][stgj] = v.z;
                Kt[stgc*8 + 4*u + 3][stgj] = v.w;
            }
            const float* vrow = g_v + (size_t)(b*S_ + k0 + stgj) * D_ + hoff + stgc*8;
            #pragma unroll
            for (int u = 0; u < 2; ++u)
                *(float4*)&Vs[stgj][stgc*8 + 4*u] = *(const float4*)(vrow + 4*u);
        }
        __syncthreads();

        float s[4][2] = {};
        #pragma unroll
        for (int d = 0; d < 64; ++d) {
            float4 qa = *(float4*)&Qt[d][ty*4];
            float2 kb = *(float2*)&Kt[d][tx*2];
            s[0][0] += qa.x*kb.x; s[0][1] += qa.x*kb.y;
            s[1][0] += qa.y*kb.x; s[1][1] += qa.y*kb.y;
            s[2][0] += qa.z*kb.x; s[2][1] += qa.z*kb.y;
            s[3][0] += qa.w*kb.x; s[3][1] += qa.w*kb.y;
        }

        const bool needmask = (k0 + 31 > q0);
        #pragma unroll
        for (int i = 0; i < 4; ++i) {
            float s0 = s[i][0] * 0.125f;
            float s1 = s[i][1] * 0.125f;
            if (needmask) {
                const int row = q0 + ty*4 + i;
                if (k0 + tx*2 + 0 > row) s0 = -1e30f;
                if (k0 + tx*2 + 1 > row) s1 = -1e30f;
            }
            float rm = fmaxf(s0, s1);
            rm = fmaxf(rm, __shfl_xor_sync(0xffffffffu, rm, 1));
            rm = fmaxf(rm, __shfl_xor_sync(0xffffffffu, rm, 2));
            rm = fmaxf(rm, __shfl_xor_sync(0xffffffffu, rm, 4));
            rm = fmaxf(rm, __shfl_xor_sync(0xffffffffu, rm, 8));
            const float nm = fmaxf(m[i], rm);
            const float alpha = __expf(m[i] - nm);
            m[i] = nm;
            const float p0 = __expf(s0 - nm);
            const float p1 = __expf(s1 - nm);
            float rs = p0 + p1;
            rs += __shfl_xor_sync(0xffffffffu, rs, 1);
            rs += __shfl_xor_sync(0xffffffffu, rs, 2);
            rs += __shfl_xor_sync(0xffffffffu, rs, 4);
            rs += __shfl_xor_sync(0xffffffffu, rs, 8);
            l[i] = l[i] * alpha + rs;
            o[i][0] *= alpha; o[i][1] *= alpha;
            o[i][2] *= alpha; o[i][3] *= alpha;
            Pt[tx*2 + 0][ty*4 + i] = p0;
            Pt[tx*2 + 1][ty*4 + i] = p1;
        }
        __syncthreads();

        #pragma unroll
        for (int j = 0; j < 32; ++j) {
            float4 vb = *(float4*)&Vs[j][tx*4];
            float pa0 = Pt[j][ty*4 + 0];
            float pa1 = Pt[j][ty*4 + 1];
            float pa2 = Pt[j][ty*4 + 2];
            float pa3 = Pt[j][ty*4 + 3];
            o[0][0] += pa0*vb.x; o[0][1] += pa0*vb.y; o[0][2] += pa0*vb.z; o[0][3] += pa0*vb.w;
            o[1][0] += pa1*vb.x; o[1][1] += pa1*vb.y; o[1][2] += pa1*vb.z; o[1][3] += pa1*vb.w;
            o[2][0] += pa2*vb.x; o[2][1] += pa2*vb.y; o[2][2] += pa2*vb.z; o[2][3] += pa2*vb.w;
            o[3][0] += pa3*vb.x; o[3][1] += pa3*vb.y; o[3][2] += pa3*vb.z; o[3][3] += pa3*vb.w;
        }
    }

    #pragma unroll
    for (int i = 0; i < 4; ++i) {
        const float inv = 1.f / l[i];
        float4 v;
        v.x = o[i][0] * inv;
        v.y = o[i][1] * inv;
        v.z = o[i][2] * inv;
        v.w = o[i][3] * inv;
        *(float4*)&g_o[(size_t)(b*S_ + q0 + ty*4 + i) * D_ + hoff + tx*4] = v;
    }
}

// ---------------------------------------------------------------------------
extern "C" void kernel_launch(void* const* d_in, const int* in_sizes, int n_in,
                              void* d_out, int out_size)
{
    (void)in_sizes; (void)n_in; (void)out_size;
    const float* x  = (const float*)d_in[0];
    const float* Wq = (const float*)d_in[1];
    const float* bq = (const float*)d_in[2];
    const float* Wk = (const float*)d_in[3];
    const float* bk = (const float*)d_in[4];
    const float* Wv = (const float*)d_in[5];
    const float* bv = (const float*)d_in[6];
    const float* Wo = (const float*)d_in[7];
    const float* bo = (const float*)d_in[8];
    float* out = (float*)d_out;

    cudaFuncSetAttribute(mma_gemm, cudaFuncAttributeMaxDynamicSharedMemorySize, GSMEM_BYTES);

    convert_split<<<(M_*D_/4 + 255)/256, 256>>>((const float4*)x, 0);
    dim3 tg(D_/32, D_/32, 4);
    transpose_split<<<tg, dim3(32, 8)>>>(Wq, Wk, Wv, Wo);

    dim3 gg(D_/128, M_/128);
    mma_gemm<<<gg, 256, GSMEM_BYTES>>>(0, 0, 0, bq, nullptr);
    mma_gemm<<<gg, 256, GSMEM_BYTES>>>(0, 1, 1, bk, nullptr);
    mma_gemm<<<gg, 256, GSMEM_BYTES>>>(0, 2, 2, bv, nullptr);

    dim3 ga(S_/64, H_, B_);
    attn_kernel<<<ga, 256>>>();

    convert_split<<<(M_*D_/4 + 255)/256, 256>>>(nullptr, 1);
    mma_gemm<<<gg, 256, GSMEM_BYTES>>>(1, 3, 3, bo, out);
}

// round 5
// speedup vs baseline: 4.7063x; 1.7772x over previous
#include <cuda_runtime.h>
#include <cuda_bf16.h>
#include <cstdint>

#define B_  2
#define S_  2048
#define D_  1024
#define H_  16
#define HD_ 64
#define M_  (B_*S_)   // 4096

// ---------------------------------------------------------------------------
// Scratch (allocation-free rule: static device globals)
// ---------------------------------------------------------------------------
__device__ float g_q[M_*D_];   // [B,S,D]
__device__ float g_k[M_*D_];
__device__ float g_v[M_*D_];
__device__ float g_o[M_*D_];   // attention output [B,S,D]

__device__ __nv_bfloat16 g_xhi[M_*D_], g_xlo[M_*D_];   // split x
__device__ __nv_bfloat16 g_ohi[M_*D_], g_olo[M_*D_];   // split g_o
__device__ __nv_bfloat16 g_wthi[4][D_*D_], g_wtlo[4][D_*D_]; // W^T split [N,K]

// ---------------------------------------------------------------------------
__device__ __forceinline__ uint32_t smem_u32(const void* p) {
    uint32_t a;
    asm("{ .reg .u64 t; cvta.to.shared.u64 t, %1; cvt.u32.u64 %0, t; }" : "=r"(a) : "l"(p));
    return a;
}

#define CP_ASYNC16(dst, src) \
    asm volatile("cp.async.cg.shared.global [%0], [%1], 16;" :: "r"(dst), "l"(src))
#define CP_COMMIT()  asm volatile("cp.async.commit_group;" ::: "memory")
#define CP_WAIT(n)   asm volatile("cp.async.wait_group %0;" :: "n"(n) : "memory")

#define LDSM_X4(r0, r1, r2, r3, addr) \
    asm volatile("ldmatrix.sync.aligned.m8n8.x4.shared.b16 {%0,%1,%2,%3}, [%4];" \
        : "=r"(r0), "=r"(r1), "=r"(r2), "=r"(r3) : "r"(addr))

#define LDSM_X4T(r0, r1, r2, r3, addr) \
    asm volatile("ldmatrix.sync.aligned.m8n8.x4.trans.shared.b16 {%0,%1,%2,%3}, [%4];" \
        : "=r"(r0), "=r"(r1), "=r"(r2), "=r"(r3) : "r"(addr))

#define MMA_BF16(d, a, b) \
    asm volatile("mma.sync.aligned.m16n8k16.row.col.f32.bf16.bf16.f32 " \
        "{%0,%1,%2,%3}, {%4,%5,%6,%7}, {%8,%9}, {%0,%1,%2,%3};" \
        : "+f"((d)[0]), "+f"((d)[1]), "+f"((d)[2]), "+f"((d)[3]) \
        : "r"((a)[0]), "r"((a)[1]), "r"((a)[2]), "r"((a)[3]), "r"((b)[0]), "r"((b)[1]))

// pack two f32 -> bf16x2 (first arg = low half)
__device__ __forceinline__ uint32_t pack_bf16x2(float lo, float hi) {
    uint32_t r;
    asm("cvt.rn.bf16x2.f32 %0, %1, %2;" : "=r"(r) : "f"(hi), "f"(lo));
    return r;
}
__device__ __forceinline__ float lo_f(uint32_t p) {
    __nv_bfloat162 v = *(__nv_bfloat162*)&p; return __bfloat162float(v.x);
}
__device__ __forceinline__ float hi_f(uint32_t p) {
    __nv_bfloat162 v = *(__nv_bfloat162*)&p; return __bfloat162float(v.y);
}

// ---------------------------------------------------------------------------
// Split-convert: fp32 -> (hi, lo) bf16.  sel=0: x (param), sel=1: g_o.
// ---------------------------------------------------------------------------
__global__ void __launch_bounds__(256) convert_split(const float4* __restrict__ xin, int sel)
{
    const int i = blockIdx.x * 256 + threadIdx.x;      // float4 index
    const float4 v = sel ? ((const float4*)g_o)[i] : xin[i];
    __nv_bfloat16* hi = sel ? g_ohi : g_xhi;
    __nv_bfloat16* lo = sel ? g_olo : g_xlo;

    __nv_bfloat16 h0 = __float2bfloat16(v.x), h1 = __float2bfloat16(v.y);
    __nv_bfloat16 h2 = __float2bfloat16(v.z), h3 = __float2bfloat16(v.w);
    __nv_bfloat16 l0 = __float2bfloat16(v.x - __bfloat162float(h0));
    __nv_bfloat16 l1 = __float2bfloat16(v.y - __bfloat162float(h1));
    __nv_bfloat16 l2 = __float2bfloat16(v.z - __bfloat162float(h2));
    __nv_bfloat16 l3 = __float2bfloat16(v.w - __bfloat162float(h3));

    __nv_bfloat162 hp[2] = {{h0, h1}, {h2, h3}};
    __nv_bfloat162 lp[2] = {{l0, l1}, {l2, l3}};
    ((uint2*)hi)[i] = *(uint2*)hp;
    ((uint2*)lo)[i] = *(uint2*)lp;
}

// ---------------------------------------------------------------------------
// Transpose + split: W[K,N] fp32 -> Wt[N,K] (hi,lo) bf16. z selects Wq/Wk/Wv/Wo.
// ---------------------------------------------------------------------------
__global__ void __launch_bounds__(256) transpose_split(
    const float* __restrict__ Wq, const float* __restrict__ Wk,
    const float* __restrict__ Wv, const float* __restrict__ Wo)
{
    const float* W = (blockIdx.z == 0) ? Wq : (blockIdx.z == 1) ? Wk
                   : (blockIdx.z == 2) ? Wv : Wo;
    __nv_bfloat16* Thi = g_wthi[blockIdx.z];
    __nv_bfloat16* Tlo = g_wtlo[blockIdx.z];

    __shared__ float tile[32][33];
    const int tx = threadIdx.x, ty = threadIdx.y;
    const int k0 = blockIdx.x * 32, n0 = blockIdx.y * 32;

    #pragma unroll
    for (int j = 0; j < 32; j += 8)
        tile[ty + j][tx] = W[(size_t)(k0 + ty + j) * D_ + n0 + tx];
    __syncthreads();
    #pragma unroll
    for (int j = 0; j < 32; j += 8) {
        float v = tile[tx][ty + j];
        __nv_bfloat16 h = __float2bfloat16(v);
        __nv_bfloat16 l = __float2bfloat16(v - __bfloat162float(h));
        const size_t idx = (size_t)(n0 + ty + j) * D_ + k0 + tx;
        Thi[idx] = h;
        Tlo[idx] = l;
    }
}

// ---------------------------------------------------------------------------
// Split-bf16 tensor-core GEMM via mma.sync (HMMA).
// ---------------------------------------------------------------------------
#define BK_   32
#define NT_   (D_ / BK_)
#define ROWE_ 40
#define TILE_BYTES (128 * ROWE_ * 2)
#define STAGE_BYTES (4 * TILE_BYTES)
#define GSMEM_BYTES (2 * STAGE_BYTES)

extern __shared__ char dsm[];

__global__ void __launch_bounds__(256, 2) mma_gemm(int asel, int wsel, int osel,
                                                   const float* __restrict__ bias,
                                                   float* __restrict__ dout)
{
    const __nv_bfloat16* Ahi = asel ? g_ohi : g_xhi;
    const __nv_bfloat16* Alo = asel ? g_olo : g_xlo;
    const __nv_bfloat16* Bhi = g_wthi[wsel];
    const __nv_bfloat16* Blo = g_wtlo[wsel];
    float* Out = (osel == 0) ? g_q : (osel == 1) ? g_k : (osel == 2) ? g_v : dout;

    const int tid  = threadIdx.x;
    const int lane = tid & 31;
    const int wid  = tid >> 5;
    const int wm   = (wid & 1) * 64;
    const int wn   = (wid >> 1) * 32;
    const int m0 = blockIdx.y * 128;
    const int n0 = blockIdx.x * 128;

    const uint32_t sb = smem_u32(dsm);

    const int cA = tid * 2, cB = tid * 2 + 1;
    const int rA = cA >> 2, qA = cA & 3;
    const int rB = cB >> 2, qB = cB & 3;

    auto issue = [&](int t) {
        const int kc = t * BK_;
        const uint32_t st = sb + (t & 1) * STAGE_BYTES;
        const __nv_bfloat16* gA[4] = {
            Ahi + (size_t)(m0 + rA) * D_ + kc + qA * 8,
            Alo + (size_t)(m0 + rA) * D_ + kc + qA * 8,
            Bhi + (size_t)(n0 + rA) * D_ + kc + qA * 8,
            Blo + (size_t)(n0 + rA) * D_ + kc + qA * 8 };
        const __nv_bfloat16* gB[4] = {
            Ahi + (size_t)(m0 + rB) * D_ + kc + qB * 8,
            Alo + (size_t)(m0 + rB) * D_ + kc + qB * 8,
            Bhi + (size_t)(n0 + rB) * D_ + kc + qB * 8,
            Blo + (size_t)(n0 + rB) * D_ + kc + qB * 8 };
        #pragma unroll
        for (int tile = 0; tile < 4; ++tile) {
            CP_ASYNC16(st + tile * TILE_BYTES + rA * (ROWE_ * 2) + qA * 16, gA[tile]);
            CP_ASYNC16(st + tile * TILE_BYTES + rB * (ROWE_ * 2) + qB * 16, gB[tile]);
        }
        CP_COMMIT();
    };

    float d[4][4][4];
    #pragma unroll
    for (int i = 0; i < 4; ++i)
        #pragma unroll
        for (int j = 0; j < 4; ++j)
            #pragma unroll
            for (int r = 0; r < 4; ++r) d[i][j][r] = 0.f;

    issue(0);

    const int aRow = lane & 15;
    const int aK8  = (lane >> 4) * 8;
    const int bRow = (lane & 7) + ((lane >> 4) & 1) * 8;
    const int bK8  = ((lane >> 3) & 1) * 8;

    for (int t = 0; t < NT_; ++t) {
        if (t + 1 < NT_) issue(t + 1);
        if (t + 1 < NT_) { CP_WAIT(1); } else { CP_WAIT(0); }
        __syncthreads();

        const uint32_t st = sb + (t & 1) * STAGE_BYTES;
        #pragma unroll
        for (int pass = 0; pass < 3; ++pass) {
            const uint32_t At = st + ((pass == 2) ? TILE_BYTES : 0);
            const uint32_t Bt = st + ((pass == 1) ? 3 : 2) * TILE_BYTES;
            #pragma unroll
            for (int ks = 0; ks < BK_; ks += 16) {
                uint32_t bfr[4][2];
                #pragma unroll
                for (int np = 0; np < 2; ++np) {
                    uint32_t addr = Bt + (uint32_t)(wn + np*16 + bRow) * (ROWE_*2)
                                  + (ks + bK8) * 2;
                    uint32_t r0, r1, r2, r3;
                    LDSM_X4(r0, r1, r2, r3, addr);
                    bfr[np*2+0][0] = r0; bfr[np*2+0][1] = r1;
                    bfr[np*2+1][0] = r2; bfr[np*2+1][1] = r3;
                }
                #pragma unroll
                for (int ms = 0; ms < 4; ++ms) {
                    uint32_t a[4];
                    uint32_t addr = At + (uint32_t)(wm + ms*16 + aRow) * (ROWE_*2)
                                  + (ks + aK8) * 2;
                    LDSM_X4(a[0], a[1], a[2], a[3], addr);
                    #pragma unroll
                    for (int ns = 0; ns < 4; ++ns)
                        MMA_BF16(d[ms][ns], a, bfr[ns]);
                }
            }
        }
        __syncthreads();
    }

    const int g = lane >> 2, q = lane & 3;
    #pragma unroll
    for (int ns = 0; ns < 4; ++ns) {
        const int col = n0 + wn + ns * 8 + q * 2;
        const float2 bv = *(const float2*)&bias[col];
        #pragma unroll
        for (int ms = 0; ms < 4; ++ms) {
            const int row = m0 + wm + ms * 16 + g;
            float2 v0 = { d[ms][ns][0] + bv.x, d[ms][ns][1] + bv.y };
            float2 v1 = { d[ms][ns][2] + bv.x, d[ms][ns][3] + bv.y };
            *(float2*)&Out[(size_t)row * D_ + col]       = v0;
            *(float2*)&Out[(size_t)(row + 8) * D_ + col] = v1;
        }
    }
}

// ---------------------------------------------------------------------------
// Tensor-core flash attention (split-bf16 HMMA), causal.
// Block: 128 q-rows of one (b,h); 8 warps, each owns m16. kv-tile = 64.
// ---------------------------------------------------------------------------
#define AROW_ 72                       // padded bf16 row (144 B)

__global__ void __launch_bounds__(256, 1) attn_kernel()
{
    __shared__ __nv_bfloat16 sKhi[64*AROW_], sKlo[64*AROW_];
    __shared__ __nv_bfloat16 sVhi[64*AROW_], sVlo[64*AROW_];

    const int qb = blockIdx.x;         // 0..15
    const int h  = blockIdx.y;
    const int b  = blockIdx.z;
    const int q0 = qb * 128;
    const size_t hoff = (size_t)h * HD_;

    const int tid  = threadIdx.x;
    const int lane = tid & 31;
    const int wid  = tid >> 5;
    const int g    = lane >> 2;
    const int qd   = lane & 3;

    const uint32_t uKhi = smem_u32(sKhi), uKlo = smem_u32(sKlo);
    const uint32_t uVhi = smem_u32(sVhi), uVlo = smem_u32(sVlo);

    // ---- Stage Q (128x64) split, into K/V buffers temporarily
    {
        const int r = tid >> 1;
        const int cb = (tid & 1) * 32;
        const float* src = g_q + (size_t)(b*S_ + q0 + r) * D_ + hoff + cb;
        __nv_bfloat16* dhi = ((r < 64) ? sKhi : sKlo) + (r & 63) * AROW_ + cb;
        __nv_bfloat16* dlo = ((r < 64) ? sVhi : sVlo) + (r & 63) * AROW_ + cb;
        #pragma unroll
        for (int u = 0; u < 32; u += 4) {
            float4 v = *(const float4*)(src + u);
            __nv_bfloat16 h0 = __float2bfloat16(v.x), h1 = __float2bfloat16(v.y);
            __nv_bfloat16 h2 = __float2bfloat16(v.z), h3 = __float2bfloat16(v.w);
            dhi[u+0] = h0; dhi[u+1] = h1; dhi[u+2] = h2; dhi[u+3] = h3;
            dlo[u+0] = __float2bfloat16(v.x - __bfloat162float(h0));
            dlo[u+1] = __float2bfloat16(v.y - __bfloat162float(h1));
            dlo[u+2] = __float2bfloat16(v.z - __bfloat162float(h2));
            dlo[u+3] = __float2bfloat16(v.w - __bfloat162float(h3));
        }
    }
    __syncthreads();

    // ---- Q fragments (A-frag layout) for 4 k-atoms, hi and lo
    uint32_t qhi[4][4], qlo[4][4];
    {
        const uint32_t hbase = (wid < 4) ? uKhi : uKlo;
        const uint32_t lbase = (wid < 4) ? uVhi : uVlo;
        const int rr = (wid & 3) * 16 + ((lane >> 3) & 1) * 8 + (lane & 7);
        #pragma unroll
        for (int kat = 0; kat < 4; ++kat) {
            const uint32_t koff = (uint32_t)(kat * 16 + ((lane >> 4) & 1) * 8) * 2;
            LDSM_X4(qhi[kat][0], qhi[kat][1], qhi[kat][2], qhi[kat][3],
                    hbase + (uint32_t)rr * (AROW_*2) + koff);
            LDSM_X4(qlo[kat][0], qlo[kat][1], qlo[kat][2], qlo[kat][3],
                    lbase + (uint32_t)rr * (AROW_*2) + koff);
        }
    }
    __syncthreads();

    float o[8][4];
    #pragma unroll
    for (int j = 0; j < 8; ++j)
        #pragma unroll
        for (int r = 0; r < 4; ++r) o[j][r] = 0.f;
    float mrow0 = -1e30f, mrow1 = -1e30f, lrow0 = 0.f, lrow1 = 0.f;

    const int wrow0 = q0 + wid * 16;

    const int kRow = ((lane >> 4) & 1) * 8 + (lane & 7);   // K ldsm row-part
    const int kK8  = ((lane >> 3) & 1) * 8;                // K ldsm k-part
    const int vRow = ((lane >> 3) & 1) * 8 + (lane & 7);   // V trans ldsm row-part
    const int vC8  = ((lane >> 4) & 1) * 8;                // V trans ldsm col-part

    const int nkt = 2 * (qb + 1);
    for (int kt = 0; kt < nkt; ++kt) {
        const int k0 = kt * 64;

        // ---- Stage K/V tile (64x64) split hi/lo
        {
            const int r = tid >> 2;
            const int cb = (tid & 3) * 16;
            const float* ks = g_k + (size_t)(b*S_ + k0 + r) * D_ + hoff + cb;
            const float* vs = g_v + (size_t)(b*S_ + k0 + r) * D_ + hoff + cb;
            __nv_bfloat16* kh = sKhi + r * AROW_ + cb;
            __nv_bfloat16* kl = sKlo + r * AROW_ + cb;
            __nv_bfloat16* vh = sVhi + r * AROW_ + cb;
            __nv_bfloat16* vl = sVlo + r * AROW_ + cb;
            #pragma unroll
            for (int u = 0; u < 16; u += 4) {
                float4 v = *(const float4*)(ks + u);
                __nv_bfloat16 h0 = __float2bfloat16(v.x), h1 = __float2bfloat16(v.y);
                __nv_bfloat16 h2 = __float2bfloat16(v.z), h3 = __float2bfloat16(v.w);
                kh[u+0]=h0; kh[u+1]=h1; kh[u+2]=h2; kh[u+3]=h3;
                kl[u+0] = __float2bfloat16(v.x - __bfloat162float(h0));
                kl[u+1] = __float2bfloat16(v.y - __bfloat162float(h1));
                kl[u+2] = __float2bfloat16(v.z - __bfloat162float(h2));
                kl[u+3] = __float2bfloat16(v.w - __bfloat162float(h3));
                float4 w = *(const float4*)(vs + u);
                __nv_bfloat16 e0 = __float2bfloat16(w.x), e1 = __float2bfloat16(w.y);
                __nv_bfloat16 e2 = __float2bfloat16(w.z), e3 = __float2bfloat16(w.w);
                vh[u+0]=e0; vh[u+1]=e1; vh[u+2]=e2; vh[u+3]=e3;
                vl[u+0] = __float2bfloat16(w.x - __bfloat162float(e0));
                vl[u+1] = __float2bfloat16(w.y - __bfloat162float(e1));
                vl[u+2] = __float2bfloat16(w.z - __bfloat162float(e2));
                vl[u+3] = __float2bfloat16(w.w - __bfloat162float(e3));
            }
        }
        __syncthreads();

        if (k0 <= wrow0 + 15) {
            // ---- S = Q @ K^T (3 split passes)
            float s[8][4];
            #pragma unroll
            for (int j = 0; j < 8; ++j)
                #pragma unroll
                for (int r = 0; r < 4; ++r) s[j][r] = 0.f;

            #pragma unroll
            for (int pass = 0; pass < 3; ++pass) {
                const uint32_t Bt = (pass == 1) ? uKlo : uKhi;
                #pragma unroll
                for (int kat = 0; kat < 4; ++kat) {
                    const uint32_t* a = (pass == 2) ? qlo[kat] : qhi[kat];
                    #pragma unroll
                    for (int jp = 0; jp < 4; ++jp) {
                        uint32_t r0, r1, r2, r3;
                        uint32_t addr = Bt + (uint32_t)(jp*16 + kRow) * (AROW_*2)
                                      + (uint32_t)(kat*16 + kK8) * 2;
                        LDSM_X4(r0, r1, r2, r3, addr);
                        uint32_t b0[2] = {r0, r1}, b1[2] = {r2, r3};
                        MMA_BF16(s[jp*2+0], a, b0);
                        MMA_BF16(s[jp*2+1], a, b1);
                    }
                }
            }

            // ---- online softmax
            const int row0 = wrow0 + g;
            const int row1 = row0 + 8;
            const bool needmask = (k0 + 63 > wrow0);
            float nm0 = mrow0, nm1 = mrow1;
            #pragma unroll
            for (int j = 0; j < 8; ++j) {
                const int col = k0 + j*8 + qd*2;
                float v0 = s[j][0] * 0.125f, v1 = s[j][1] * 0.125f;
                float v2 = s[j][2] * 0.125f, v3 = s[j][3] * 0.125f;
                if (needmask) {
                    if (col + 0 > row0) v0 = -1e30f;
                    if (col + 1 > row0) v1 = -1e30f;
                    if (col + 0 > row1) v2 = -1e30f;
                    if (col + 1 > row1) v3 = -1e30f;
                }
                s[j][0] = v0; s[j][1] = v1; s[j][2] = v2; s[j][3] = v3;
                nm0 = fmaxf(nm0, fmaxf(v0, v1));
                nm1 = fmaxf(nm1, fmaxf(v2, v3));
            }
            nm0 = fmaxf(nm0, __shfl_xor_sync(0xffffffffu, nm0, 1));
            nm0 = fmaxf(nm0, __shfl_xor_sync(0xffffffffu, nm0, 2));
            nm1 = fmaxf(nm1, __shfl_xor_sync(0xffffffffu, nm1, 1));
            nm1 = fmaxf(nm1, __shfl_xor_sync(0xffffffffu, nm1, 2));

            const float alpha0 = __expf(mrow0 - nm0);
            const float alpha1 = __expf(mrow1 - nm1);
            mrow0 = nm0; mrow1 = nm1;

            uint32_t phi[4][4], plo[4][4];
            float ps0 = 0.f, ps1 = 0.f;
            #pragma unroll
            for (int jp = 0; jp < 4; ++jp) {
                #pragma unroll
                for (int half = 0; half < 2; ++half) {
                    const int j = jp*2 + half;
                    const float p0 = __expf(s[j][0] - nm0);
                    const float p1 = __expf(s[j][1] - nm0);
                    const float p2 = __expf(s[j][2] - nm1);
                    const float p3 = __expf(s[j][3] - nm1);
                    ps0 += p0 + p1; ps1 += p2 + p3;
                    // A-frag: a0={row g,k even/odd}, a1={row g+8}, a2/a3 = k+8
                    const uint32_t h01 = pack_bf16x2(p0, p1);
                    const uint32_t h23 = pack_bf16x2(p2, p3);
                    phi[jp][half*1 + 0 + (half ? 2 : 0)] = 0; // overwritten just below
                    phi[jp][0 + half*2] = h01;       // a0 (half0) / a2 (half1)
                    phi[jp][1 + half*2] = h23;       // a1 (half0) / a3 (half1)
                    plo[jp][0 + half*2] = pack_bf16x2(p0 - lo_f(h01), p1 - hi_f(h01));
                    plo[jp][1 + half*2] = pack_bf16x2(p2 - lo_f(h23), p3 - hi_f(h23));
                }
            }
            ps0 += __shfl_xor_sync(0xffffffffu, ps0, 1);
            ps0 += __shfl_xor_sync(0xffffffffu, ps0, 2);
            ps1 += __shfl_xor_sync(0xffffffffu, ps1, 1);
            ps1 += __shfl_xor_sync(0xffffffffu, ps1, 2);
            lrow0 = lrow0 * alpha0 + ps0;
            lrow1 = lrow1 * alpha1 + ps1;
            #pragma unroll
            for (int j = 0; j < 8; ++j) {
                o[j][0] *= alpha0; o[j][1] *= alpha0;
                o[j][2] *= alpha1; o[j][3] *= alpha1;
            }

            // ---- O += P @ V (3 split passes), B via ldmatrix.trans on V
            #pragma unroll
            for (int pass = 0; pass < 3; ++pass) {
                const uint32_t Bt = (pass == 1) ? uVlo : uVhi;
                #pragma unroll
                for (int kat = 0; kat < 4; ++kat) {
                    const uint32_t* a = (pass == 2) ? plo[kat] : phi[kat];
                    #pragma unroll
                    for (int jp = 0; jp < 4; ++jp) {
                        uint32_t r0, r1, r2, r3;
                        uint32_t addr = Bt + (uint32_t)(kat*16 + vRow) * (AROW_*2)
                                      + (uint32_t)(jp*16 + vC8) * 2;
                        LDSM_X4T(r0, r1, r2, r3, addr);
                        uint32_t b0[2] = {r0, r1}, b1[2] = {r2, r3};
                        MMA_BF16(o[jp*2+0], a, b0);
                        MMA_BF16(o[jp*2+1], a, b1);
                    }
                }
            }
        }
        __syncthreads();
    }

    // ---- normalize + write [B,S,D]
    const float inv0 = 1.f / lrow0;
    const float inv1 = 1.f / lrow1;
    const int row0 = q0 + wid*16 + g;
    #pragma unroll
    for (int j = 0; j < 8; ++j) {
        const int col = j*8 + qd*2;
        float2 v0 = { o[j][0] * inv0, o[j][1] * inv0 };
        float2 v1 = { o[j][2] * inv1, o[j][3] * inv1 };
        *(float2*)&g_o[(size_t)(b*S_ + row0) * D_ + hoff + col]     = v0;
        *(float2*)&g_o[(size_t)(b*S_ + row0 + 8) * D_ + hoff + col] = v1;
    }
}

// ---------------------------------------------------------------------------
extern "C" void kernel_launch(void* const* d_in, const int* in_sizes, int n_in,
                              void* d_out, int out_size)
{
    (void)in_sizes; (void)n_in; (void)out_size;
    const float* x  = (const float*)d_in[0];
    const float* Wq = (const float*)d_in[1];
    const float* bq = (const float*)d_in[2];
    const float* Wk = (const float*)d_in[3];
    const float* bk = (const float*)d_in[4];
    const float* Wv = (const float*)d_in[5];
    const float* bv = (const float*)d_in[6];
    const float* Wo = (const float*)d_in[7];
    const float* bo = (const float*)d_in[8];
    float* out = (float*)d_out;

    cudaFuncSetAttribute(mma_gemm, cudaFuncAttributeMaxDynamicSharedMemorySize, GSMEM_BYTES);

    convert_split<<<(M_*D_/4 + 255)/256, 256>>>((const float4*)x, 0);
    dim3 tg(D_/32, D_/32, 4);
    transpose_split<<<tg, dim3(32, 8)>>>(Wq, Wk, Wv, Wo);

    dim3 gg(D_/128, M_/128);
    mma_gemm<<<gg, 256, GSMEM_BYTES>>>(0, 0, 0, bq, nullptr);
    mma_gemm<<<gg, 256, GSMEM_BYTES>>>(0, 1, 1, bk, nullptr);
    mma_gemm<<<gg, 256, GSMEM_BYTES>>>(0, 2, 2, bv, nullptr);

    dim3 ga(S_/128, H_, B_);
    attn_kernel<<<ga, 256>>>();

    convert_split<<<(M_*D_/4 + 255)/256, 256>>>(nullptr, 1);
    mma_gemm<<<gg, 256, GSMEM_BYTES>>>(1, 3, 3, bo, out);
}

// round 6
// speedup vs baseline: 5.8493x; 1.2429x over previous
#include <cuda_runtime.h>
#include <cuda_bf16.h>
#include <cuda_fp16.h>
#include <cstdint>

#define B_  2
#define S_  2048
#define D_  1024
#define H_  16
#define HD_ 64
#define M_  (B_*S_)   // 4096

// ---------------------------------------------------------------------------
// Scratch (allocation-free rule: static device globals)
// ---------------------------------------------------------------------------
__device__ float g_q[M_*D_];   // [B,S,D]
__device__ float g_k[M_*D_];
__device__ float g_v[M_*D_];
__device__ float g_o[M_*D_];   // attention output [B,S,D]

__device__ __half g_xh16[M_*D_];              // fp16(x)
__device__ __half g_oh16[M_*D_];              // fp16(g_o)
__device__ __half g_wth[4][D_*D_], g_wtl[4][D_*D_];  // W^T split fp16 [N,K]

// ---------------------------------------------------------------------------
__device__ __forceinline__ uint32_t smem_u32(const void* p) {
    uint32_t a;
    asm("{ .reg .u64 t; cvta.to.shared.u64 t, %1; cvt.u32.u64 %0, t; }" : "=r"(a) : "l"(p));
    return a;
}

#define CP_ASYNC16(dst, src) \
    asm volatile("cp.async.cg.shared.global [%0], [%1], 16;" :: "r"(dst), "l"(src))
#define CP_COMMIT()  asm volatile("cp.async.commit_group;" ::: "memory")
#define CP_WAIT(n)   asm volatile("cp.async.wait_group %0;" :: "n"(n) : "memory")

#define LDSM_X4(r0, r1, r2, r3, addr) \
    asm volatile("ldmatrix.sync.aligned.m8n8.x4.shared.b16 {%0,%1,%2,%3}, [%4];" \
        : "=r"(r0), "=r"(r1), "=r"(r2), "=r"(r3) : "r"(addr))

#define LDSM_X4T(r0, r1, r2, r3, addr) \
    asm volatile("ldmatrix.sync.aligned.m8n8.x4.trans.shared.b16 {%0,%1,%2,%3}, [%4];" \
        : "=r"(r0), "=r"(r1), "=r"(r2), "=r"(r3) : "r"(addr))

#define MMA_BF16(d, a, b) \
    asm volatile("mma.sync.aligned.m16n8k16.row.col.f32.bf16.bf16.f32 " \
        "{%0,%1,%2,%3}, {%4,%5,%6,%7}, {%8,%9}, {%0,%1,%2,%3};" \
        : "+f"((d)[0]), "+f"((d)[1]), "+f"((d)[2]), "+f"((d)[3]) \
        : "r"((a)[0]), "r"((a)[1]), "r"((a)[2]), "r"((a)[3]), "r"((b)[0]), "r"((b)[1]))

#define MMA_F16(d, a, b) \
    asm volatile("mma.sync.aligned.m16n8k16.row.col.f32.f16.f16.f32 " \
        "{%0,%1,%2,%3}, {%4,%5,%6,%7}, {%8,%9}, {%0,%1,%2,%3};" \
        : "+f"((d)[0]), "+f"((d)[1]), "+f"((d)[2]), "+f"((d)[3]) \
        : "r"((a)[0]), "r"((a)[1]), "r"((a)[2]), "r"((a)[3]), "r"((b)[0]), "r"((b)[1]))

// pack two f32 -> bf16x2 (first arg = low half)
__device__ __forceinline__ uint32_t pack_bf16x2(float lo, float hi) {
    uint32_t r;
    asm("cvt.rn.bf16x2.f32 %0, %1, %2;" : "=r"(r) : "f"(hi), "f"(lo));
    return r;
}
__device__ __forceinline__ float lo_f(uint32_t p) {
    __nv_bfloat162 v = *(__nv_bfloat162*)&p; return __bfloat162float(v.x);
}
__device__ __forceinline__ float hi_f(uint32_t p) {
    __nv_bfloat162 v = *(__nv_bfloat162*)&p; return __bfloat162float(v.y);
}

// ---------------------------------------------------------------------------
// Convert fp32 -> fp16.  sel=0: x (param) -> g_xh16, sel=1: g_o -> g_oh16.
// ---------------------------------------------------------------------------
__global__ void __launch_bounds__(256) convert_h(const float4* __restrict__ xin, int sel)
{
    const int i = blockIdx.x * 256 + threadIdx.x;
    const float4 v = sel ? ((const float4*)g_o)[i] : xin[i];
    __half* dst = sel ? g_oh16 : g_xh16;
    __half2 p0 = __floats2half2_rn(v.x, v.y);
    __half2 p1 = __floats2half2_rn(v.z, v.w);
    uint2 u; u.x = *(uint32_t*)&p0; u.y = *(uint32_t*)&p1;
    ((uint2*)dst)[i] = u;
}

// ---------------------------------------------------------------------------
// Transpose + split: W[K,N] fp32 -> Wt[N,K] (hi,lo) fp16. z selects Wq/Wk/Wv/Wo.
// ---------------------------------------------------------------------------
__global__ void __launch_bounds__(256) transpose_split(
    const float* __restrict__ Wq, const float* __restrict__ Wk,
    const float* __restrict__ Wv, const float* __restrict__ Wo)
{
    const float* W = (blockIdx.z == 0) ? Wq : (blockIdx.z == 1) ? Wk
                   : (blockIdx.z == 2) ? Wv : Wo;
    __half* Thi = g_wth[blockIdx.z];
    __half* Tlo = g_wtl[blockIdx.z];

    __shared__ float tile[32][33];
    const int tx = threadIdx.x, ty = threadIdx.y;
    const int k0 = blockIdx.x * 32, n0 = blockIdx.y * 32;

    #pragma unroll
    for (int j = 0; j < 32; j += 8)
        tile[ty + j][tx] = W[(size_t)(k0 + ty + j) * D_ + n0 + tx];
    __syncthreads();
    #pragma unroll
    for (int j = 0; j < 32; j += 8) {
        float v = tile[tx][ty + j];
        __half h = __float2half(v);
        __half l = __float2half(v - __half2float(h));
        const size_t idx = (size_t)(n0 + ty + j) * D_ + k0 + tx;
        Thi[idx] = h;
        Tlo[idx] = l;
    }
}

// ---------------------------------------------------------------------------
// 2-pass split-fp16 GEMM: Out = A_fp16 * (Bh + Bl)^T + bias (fp32 accum).
// Tile 128x128, 8 warps (64x32 each), BK=32, cp.async double-buffered.
// mode 0: QKV (blockIdx.z selects W/bias/out, A = g_xh16)
// mode 1: out projection (W=3, A = g_oh16, out = dout)
// ---------------------------------------------------------------------------
#define BK_   32
#define NT_   (D_ / BK_)
#define ROWE_ 40                         // 32 halves + 8 pad = 80 bytes
#define TILE_BYTES (128 * ROWE_ * 2)     // 10240
#define STAGE_BYTES (3 * TILE_BYTES)     // 30720 (A, Bh, Bl)
#define GSMEM_BYTES (2 * STAGE_BYTES)    // 61440

extern __shared__ char dsm[];

__global__ void __launch_bounds__(256, 2) mma_gemm(int mode,
    const float* __restrict__ b0, const float* __restrict__ b1,
    const float* __restrict__ b2, float* __restrict__ dout)
{
    const int z = mode ? 3 : blockIdx.z;
    const __half* A   = mode ? g_oh16 : g_xh16;
    const __half* Bh  = g_wth[z];
    const __half* Bl  = g_wtl[z];
    const float* bias = mode ? b0 : (z == 0 ? b0 : (z == 1 ? b1 : b2));
    float* Out = mode ? dout : (z == 0 ? g_q : (z == 1 ? g_k : g_v));

    const int tid  = threadIdx.x;
    const int lane = tid & 31;
    const int wid  = tid >> 5;
    const int wm   = (wid & 1) * 64;
    const int wn   = (wid >> 1) * 32;
    const int m0 = blockIdx.y * 128;
    const int n0 = blockIdx.x * 128;

    const uint32_t sb = smem_u32(dsm);

    const int cA = tid * 2, cB = tid * 2 + 1;
    const int rA = cA >> 2, qA = cA & 3;
    const int rB = cB >> 2, qB = cB & 3;

    auto issue = [&](int t) {
        const int kc = t * BK_;
        const uint32_t st = sb + (t & 1) * STAGE_BYTES;
        CP_ASYNC16(st + rA * 80 + qA * 16, A  + (size_t)(m0 + rA) * D_ + kc + qA * 8);
        CP_ASYNC16(st + rB * 80 + qB * 16, A  + (size_t)(m0 + rB) * D_ + kc + qB * 8);
        CP_ASYNC16(st + TILE_BYTES   + rA * 80 + qA * 16, Bh + (size_t)(n0 + rA) * D_ + kc + qA * 8);
        CP_ASYNC16(st + TILE_BYTES   + rB * 80 + qB * 16, Bh + (size_t)(n0 + rB) * D_ + kc + qB * 8);
        CP_ASYNC16(st + 2*TILE_BYTES + rA * 80 + qA * 16, Bl + (size_t)(n0 + rA) * D_ + kc + qA * 8);
        CP_ASYNC16(st + 2*TILE_BYTES + rB * 80 + qB * 16, Bl + (size_t)(n0 + rB) * D_ + kc + qB * 8);
        CP_COMMIT();
    };

    float d[4][4][4];
    #pragma unroll
    for (int i = 0; i < 4; ++i)
        #pragma unroll
        for (int j = 0; j < 4; ++j)
            #pragma unroll
            for (int r = 0; r < 4; ++r) d[i][j][r] = 0.f;

    issue(0);

    const int aRow = lane & 15;
    const int aK8  = (lane >> 4) * 8;
    const int bRow = (lane & 7) + ((lane >> 4) & 1) * 8;
    const int bK8  = ((lane >> 3) & 1) * 8;

    for (int t = 0; t < NT_; ++t) {
        if (t + 1 < NT_) { issue(t + 1); CP_WAIT(1); } else { CP_WAIT(0); }
        __syncthreads();

        const uint32_t st = sb + (t & 1) * STAGE_BYTES;
        #pragma unroll
        for (int ks = 0; ks < BK_; ks += 16) {
            // A fragments: 4 m-atoms, loaded once, reused for both passes
            uint32_t a[4][4];
            #pragma unroll
            for (int ms = 0; ms < 4; ++ms) {
                uint32_t addr = st + (uint32_t)(wm + ms*16 + aRow) * 80
                              + (uint32_t)(ks + aK8) * 2;
                LDSM_X4(a[ms][0], a[ms][1], a[ms][2], a[ms][3], addr);
            }
            // B fragments hi & lo
            uint32_t bh[4][2], bl[4][2];
            #pragma unroll
            for (int np = 0; np < 2; ++np) {
                uint32_t r0, r1, r2, r3;
                uint32_t boff = (uint32_t)(wn + np*16 + bRow) * 80
                              + (uint32_t)(ks + bK8) * 2;
                LDSM_X4(r0, r1, r2, r3, st + TILE_BYTES + boff);
                bh[np*2+0][0] = r0; bh[np*2+0][1] = r1;
                bh[np*2+1][0] = r2; bh[np*2+1][1] = r3;
                LDSM_X4(r0, r1, r2, r3, st + 2*TILE_BYTES + boff);
                bl[np*2+0][0] = r0; bl[np*2+0][1] = r1;
                bl[np*2+1][0] = r2; bl[np*2+1][1] = r3;
            }
            #pragma unroll
            for (int ms = 0; ms < 4; ++ms)
                #pragma unroll
                for (int ns = 0; ns < 4; ++ns) {
                    MMA_F16(d[ms][ns], a[ms], bh[ns]);
                    MMA_F16(d[ms][ns], a[ms], bl[ns]);
                }
        }
        __syncthreads();
    }

    const int g = lane >> 2, q = lane & 3;
    #pragma unroll
    for (int ns = 0; ns < 4; ++ns) {
        const int col = n0 + wn + ns * 8 + q * 2;
        const float2 bv = *(const float2*)&bias[col];
        #pragma unroll
        for (int ms = 0; ms < 4; ++ms) {
            const int row = m0 + wm + ms * 16 + g;
            float2 v0 = { d[ms][ns][0] + bv.x, d[ms][ns][1] + bv.y };
            float2 v1 = { d[ms][ns][2] + bv.x, d[ms][ns][3] + bv.y };
            *(float2*)&Out[(size_t)row * D_ + col]       = v0;
            *(float2*)&Out[(size_t)(row + 8) * D_ + col] = v1;
        }
    }
}

// ---------------------------------------------------------------------------
// Tensor-core flash attention (split-bf16 HMMA, 3-pass), causal. UNCHANGED (R5).
// ---------------------------------------------------------------------------
#define AROW_ 72                       // padded bf16 row (144 B)

__global__ void __launch_bounds__(256, 1) attn_kernel()
{
    __shared__ __nv_bfloat16 sKhi[64*AROW_], sKlo[64*AROW_];
    __shared__ __nv_bfloat16 sVhi[64*AROW_], sVlo[64*AROW_];

    const int qb = blockIdx.x;
    const int h  = blockIdx.y;
    const int b  = blockIdx.z;
    const int q0 = qb * 128;
    const size_t hoff = (size_t)h * HD_;

    const int tid  = threadIdx.x;
    const int lane = tid & 31;
    const int wid  = tid >> 5;
    const int g    = lane >> 2;
    const int qd   = lane & 3;

    const uint32_t uKhi = smem_u32(sKhi), uKlo = smem_u32(sKlo);
    const uint32_t uVhi = smem_u32(sVhi), uVlo = smem_u32(sVlo);

    // Stage Q (128x64) split, into K/V buffers temporarily
    {
        const int r = tid >> 1;
        const int cb = (tid & 1) * 32;
        const float* src = g_q + (size_t)(b*S_ + q0 + r) * D_ + hoff + cb;
        __nv_bfloat16* dhi = ((r < 64) ? sKhi : sKlo) + (r & 63) * AROW_ + cb;
        __nv_bfloat16* dlo = ((r < 64) ? sVhi : sVlo) + (r & 63) * AROW_ + cb;
        #pragma unroll
        for (int u = 0; u < 32; u += 4) {
            float4 v = *(const float4*)(src + u);
            __nv_bfloat16 h0 = __float2bfloat16(v.x), h1 = __float2bfloat16(v.y);
            __nv_bfloat16 h2 = __float2bfloat16(v.z), h3 = __float2bfloat16(v.w);
            dhi[u+0] = h0; dhi[u+1] = h1; dhi[u+2] = h2; dhi[u+3] = h3;
            dlo[u+0] = __float2bfloat16(v.x - __bfloat162float(h0));
            dlo[u+1] = __float2bfloat16(v.y - __bfloat162float(h1));
            dlo[u+2] = __float2bfloat16(v.z - __bfloat162float(h2));
            dlo[u+3] = __float2bfloat16(v.w - __bfloat162float(h3));
        }
    }
    __syncthreads();

    uint32_t qhi[4][4], qlo[4][4];
    {
        const uint32_t hbase = (wid < 4) ? uKhi : uKlo;
        const uint32_t lbase = (wid < 4) ? uVhi : uVlo;
        const int rr = (wid & 3) * 16 + ((lane >> 3) & 1) * 8 + (lane & 7);
        #pragma unroll
        for (int kat = 0; kat < 4; ++kat) {
            const uint32_t koff = (uint32_t)(kat * 16 + ((lane >> 4) & 1) * 8) * 2;
            LDSM_X4(qhi[kat][0], qhi[kat][1], qhi[kat][2], qhi[kat][3],
                    hbase + (uint32_t)rr * (AROW_*2) + koff);
            LDSM_X4(qlo[kat][0], qlo[kat][1], qlo[kat][2], qlo[kat][3],
                    lbase + (uint32_t)rr * (AROW_*2) + koff);
        }
    }
    __syncthreads();

    float o[8][4];
    #pragma unroll
    for (int j = 0; j < 8; ++j)
        #pragma unroll
        for (int r = 0; r < 4; ++r) o[j][r] = 0.f;
    float mrow0 = -1e30f, mrow1 = -1e30f, lrow0 = 0.f, lrow1 = 0.f;

    const int wrow0 = q0 + wid * 16;

    const int kRow = ((lane >> 4) & 1) * 8 + (lane & 7);
    const int kK8  = ((lane >> 3) & 1) * 8;
    const int vRow = ((lane >> 3) & 1) * 8 + (lane & 7);
    const int vC8  = ((lane >> 4) & 1) * 8;

    const int nkt = 2 * (qb + 1);
    for (int kt = 0; kt < nkt; ++kt) {
        const int k0 = kt * 64;

        {
            const int r = tid >> 2;
            const int cb = (tid & 3) * 16;
            const float* ks = g_k + (size_t)(b*S_ + k0 + r) * D_ + hoff + cb;
            const float* vs = g_v + (size_t)(b*S_ + k0 + r) * D_ + hoff + cb;
            __nv_bfloat16* kh = sKhi + r * AROW_ + cb;
            __nv_bfloat16* kl = sKlo + r * AROW_ + cb;
            __nv_bfloat16* vh = sVhi + r * AROW_ + cb;
            __nv_bfloat16* vl = sVlo + r * AROW_ + cb;
            #pragma unroll
            for (int u = 0; u < 16; u += 4) {
                float4 v = *(const float4*)(ks + u);
                __nv_bfloat16 h0 = __float2bfloat16(v.x), h1 = __float2bfloat16(v.y);
                __nv_bfloat16 h2 = __float2bfloat16(v.z), h3 = __float2bfloat16(v.w);
                kh[u+0]=h0; kh[u+1]=h1; kh[u+2]=h2; kh[u+3]=h3;
                kl[u+0] = __float2bfloat16(v.x - __bfloat162float(h0));
                kl[u+1] = __float2bfloat16(v.y - __bfloat162float(h1));
                kl[u+2] = __float2bfloat16(v.z - __bfloat162float(h2));
                kl[u+3] = __float2bfloat16(v.w - __bfloat162float(h3));
                float4 w = *(const float4*)(vs + u);
                __nv_bfloat16 e0 = __float2bfloat16(w.x), e1 = __float2bfloat16(w.y);
                __nv_bfloat16 e2 = __float2bfloat16(w.z), e3 = __float2bfloat16(w.w);
                vh[u+0]=e0; vh[u+1]=e1; vh[u+2]=e2; vh[u+3]=e3;
                vl[u+0] = __float2bfloat16(w.x - __bfloat162float(e0));
                vl[u+1] = __float2bfloat16(w.y - __bfloat162float(e1));
                vl[u+2] = __float2bfloat16(w.z - __bfloat162float(e2));
                vl[u+3] = __float2bfloat16(w.w - __bfloat162float(e3));
            }
        }
        __syncthreads();

        if (k0 <= wrow0 + 15) {
            float s[8][4];
            #pragma unroll
            for (int j = 0; j < 8; ++j)
                #pragma unroll
                for (int r = 0; r < 4; ++r) s[j][r] = 0.f;

            #pragma unroll
            for (int pass = 0; pass < 3; ++pass) {
                const uint32_t Bt = (pass == 1) ? uKlo : uKhi;
                #pragma unroll
                for (int kat = 0; kat < 4; ++kat) {
                    const uint32_t* a = (pass == 2) ? qlo[kat] : qhi[kat];
                    #pragma unroll
                    for (int jp = 0; jp < 4; ++jp) {
                        uint32_t r0, r1, r2, r3;
                        uint32_t addr = Bt + (uint32_t)(jp*16 + kRow) * (AROW_*2)
                                      + (uint32_t)(kat*16 + kK8) * 2;
                        LDSM_X4(r0, r1, r2, r3, addr);
                        uint32_t b0[2] = {r0, r1}, b1[2] = {r2, r3};
                        MMA_BF16(s[jp*2+0], a, b0);
                        MMA_BF16(s[jp*2+1], a, b1);
                    }
                }
            }

            const int row0 = wrow0 + g;
            const int row1 = row0 + 8;
            const bool needmask = (k0 + 63 > wrow0);
            float nm0 = mrow0, nm1 = mrow1;
            #pragma unroll
            for (int j = 0; j < 8; ++j) {
                const int col = k0 + j*8 + qd*2;
                float v0 = s[j][0] * 0.125f, v1 = s[j][1] * 0.125f;
                float v2 = s[j][2] * 0.125f, v3 = s[j][3] * 0.125f;
                if (needmask) {
                    if (col + 0 > row0) v0 = -1e30f;
                    if (col + 1 > row0) v1 = -1e30f;
                    if (col + 0 > row1) v2 = -1e30f;
                    if (col + 1 > row1) v3 = -1e30f;
                }
                s[j][0] = v0; s[j][1] = v1; s[j][2] = v2; s[j][3] = v3;
                nm0 = fmaxf(nm0, fmaxf(v0, v1));
                nm1 = fmaxf(nm1, fmaxf(v2, v3));
            }
            nm0 = fmaxf(nm0, __shfl_xor_sync(0xffffffffu, nm0, 1));
            nm0 = fmaxf(nm0, __shfl_xor_sync(0xffffffffu, nm0, 2));
            nm1 = fmaxf(nm1, __shfl_xor_sync(0xffffffffu, nm1, 1));
            nm1 = fmaxf(nm1, __shfl_xor_sync(0xffffffffu, nm1, 2));

            const float alpha0 = __expf(mrow0 - nm0);
            const float alpha1 = __expf(mrow1 - nm1);
            mrow0 = nm0; mrow1 = nm1;

            uint32_t phi[4][4], plo[4][4];
            float ps0 = 0.f, ps1 = 0.f;
            #pragma unroll
            for (int jp = 0; jp < 4; ++jp) {
                #pragma unroll
                for (int half = 0; half < 2; ++half) {
                    const int j = jp*2 + half;
                    const float p0 = __expf(s[j][0] - nm0);
                    const float p1 = __expf(s[j][1] - nm0);
                    const float p2 = __expf(s[j][2] - nm1);
                    const float p3 = __expf(s[j][3] - nm1);
                    ps0 += p0 + p1; ps1 += p2 + p3;
                    const uint32_t h01 = pack_bf16x2(p0, p1);
                    const uint32_t h23 = pack_bf16x2(p2, p3);
                    phi[jp][0 + half*2] = h01;
                    phi[jp][1 + half*2] = h23;
                    plo[jp][0 + half*2] = pack_bf16x2(p0 - lo_f(h01), p1 - hi_f(h01));
                    plo[jp][1 + half*2] = pack_bf16x2(p2 - lo_f(h23), p3 - hi_f(h23));
                }
            }
            ps0 += __shfl_xor_sync(0xffffffffu, ps0, 1);
            ps0 += __shfl_xor_sync(0xffffffffu, ps0, 2);
            ps1 += __shfl_xor_sync(0xffffffffu, ps1, 1);
            ps1 += __shfl_xor_sync(0xffffffffu, ps1, 2);
            lrow0 = lrow0 * alpha0 + ps0;
            lrow1 = lrow1 * alpha1 + ps1;
            #pragma unroll
            for (int j = 0; j < 8; ++j) {
                o[j][0] *= alpha0; o[j][1] *= alpha0;
                o[j][2] *= alpha1; o[j][3] *= alpha1;
            }

            #pragma unroll
            for (int pass = 0; pass < 3; ++pass) {
                const uint32_t Bt = (pass == 1) ? uVlo : uVhi;
                #pragma unroll
                for (int kat = 0; kat < 4; ++kat) {
                    const uint32_t* a = (pass == 2) ? plo[kat] : phi[kat];
                    #pragma unroll
                    for (int jp = 0; jp < 4; ++jp) {
                        uint32_t r0, r1, r2, r3;
                        uint32_t addr = Bt + (uint32_t)(kat*16 + vRow) * (AROW_*2)
                                      + (uint32_t)(jp*16 + vC8) * 2;
                        LDSM_X4T(r0, r1, r2, r3, addr);
                        uint32_t b0[2] = {r0, r1}, b1[2] = {r2, r3};
                        MMA_BF16(o[jp*2+0], a, b0);
                        MMA_BF16(o[jp*2+1], a, b1);
                    }
                }
            }
        }
        __syncthreads();
    }

    const float inv0 = 1.f / lrow0;
    const float inv1 = 1.f / lrow1;
    const int row0 = q0 + wid*16 + g;
    #pragma unroll
    for (int j = 0; j < 8; ++j) {
        const int col = j*8 + qd*2;
        float2 v0 = { o[j][0] * inv0, o[j][1] * inv0 };
        float2 v1 = { o[j][2] * inv1, o[j][3] * inv1 };
        *(float2*)&g_o[(size_t)(b*S_ + row0) * D_ + hoff + col]     = v0;
        *(float2*)&g_o[(size_t)(b*S_ + row0 + 8) * D_ + hoff + col] = v1;
    }
}

// ---------------------------------------------------------------------------
extern "C" void kernel_launch(void* const* d_in, const int* in_sizes, int n_in,
                              void* d_out, int out_size)
{
    (void)in_sizes; (void)n_in; (void)out_size;
    const float* x  = (const float*)d_in[0];
    const float* Wq = (const float*)d_in[1];
    const float* bq = (const float*)d_in[2];
    const float* Wk = (const float*)d_in[3];
    const float* bk = (const float*)d_in[4];
    const float* Wv = (const float*)d_in[5];
    const float* bv = (const float*)d_in[6];
    const float* Wo = (const float*)d_in[7];
    const float* bo = (const float*)d_in[8];
    float* out = (float*)d_out;

    cudaFuncSetAttribute(mma_gemm, cudaFuncAttributeMaxDynamicSharedMemorySize, GSMEM_BYTES);

    convert_h<<<(M_*D_/4 + 255)/256, 256>>>((const float4*)x, 0);
    dim3 tg(D_/32, D_/32, 4);
    transpose_split<<<tg, dim3(32, 8)>>>(Wq, Wk, Wv, Wo);

    // fused QKV projections (grid.z selects head)
    dim3 gq(D_/128, M_/128, 3);
    mma_gemm<<<gq, 256, GSMEM_BYTES>>>(0, bq, bk, bv, nullptr);

    dim3 ga(S_/128, H_, B_);
    attn_kernel<<<ga, 256>>>();

    convert_h<<<(M_*D_/4 + 255)/256, 256>>>(nullptr, 1);
    dim3 go(D_/128, M_/128, 1);
    mma_gemm<<<go, 256, GSMEM_BYTES>>>(1, bo, nullptr, nullptr, out);
}

// round 7
// speedup vs baseline: 6.4643x; 1.1051x over previous
#include <cuda_runtime.h>
#include <cuda_bf16.h>
#include <cuda_fp16.h>
#include <cstdint>

#define B_  2
#define S_  2048
#define D_  1024
#define H_  16
#define HD_ 64
#define M_  (B_*S_)   // 4096

// ---------------------------------------------------------------------------
// Scratch (allocation-free rule: static device globals)
// ---------------------------------------------------------------------------
__device__ float g_q[M_*D_];   // [B,S,D]
__device__ float g_k[M_*D_];
__device__ float g_v[M_*D_];
__device__ float g_o[M_*D_];   // attention output [B,S,D]

__device__ __half g_xh16[M_*D_];              // fp16(x)
__device__ __half g_oh16[M_*D_];              // fp16(g_o)
__device__ __half g_wth[4][D_*D_], g_wtl[4][D_*D_];  // W^T split fp16 [N,K]

// split-bf16 copies of q/k/v for tensor attention
__device__ __nv_bfloat16 g_qh[M_*D_], g_ql[M_*D_];
__device__ __nv_bfloat16 g_kh[M_*D_], g_kl[M_*D_];
__device__ __nv_bfloat16 g_vh[M_*D_], g_vl[M_*D_];

// ---------------------------------------------------------------------------
__device__ __forceinline__ uint32_t smem_u32(const void* p) {
    uint32_t a;
    asm("{ .reg .u64 t; cvta.to.shared.u64 t, %1; cvt.u32.u64 %0, t; }" : "=r"(a) : "l"(p));
    return a;
}

#define CP_ASYNC16(dst, src) \
    asm volatile("cp.async.cg.shared.global [%0], [%1], 16;" :: "r"(dst), "l"(src))
#define CP_COMMIT()  asm volatile("cp.async.commit_group;" ::: "memory")
#define CP_WAIT(n)   asm volatile("cp.async.wait_group %0;" :: "n"(n) : "memory")

#define LDSM_X4(r0, r1, r2, r3, addr) \
    asm volatile("ldmatrix.sync.aligned.m8n8.x4.shared.b16 {%0,%1,%2,%3}, [%4];" \
        : "=r"(r0), "=r"(r1), "=r"(r2), "=r"(r3) : "r"(addr))

#define LDSM_X4T(r0, r1, r2, r3, addr) \
    asm volatile("ldmatrix.sync.aligned.m8n8.x4.trans.shared.b16 {%0,%1,%2,%3}, [%4];" \
        : "=r"(r0), "=r"(r1), "=r"(r2), "=r"(r3) : "r"(addr))

#define MMA_BF16(d, a, b) \
    asm volatile("mma.sync.aligned.m16n8k16.row.col.f32.bf16.bf16.f32 " \
        "{%0,%1,%2,%3}, {%4,%5,%6,%7}, {%8,%9}, {%0,%1,%2,%3};" \
        : "+f"((d)[0]), "+f"((d)[1]), "+f"((d)[2]), "+f"((d)[3]) \
        : "r"((a)[0]), "r"((a)[1]), "r"((a)[2]), "r"((a)[3]), "r"((b)[0]), "r"((b)[1]))

#define MMA_F16(d, a, b) \
    asm volatile("mma.sync.aligned.m16n8k16.row.col.f32.f16.f16.f32 " \
        "{%0,%1,%2,%3}, {%4,%5,%6,%7}, {%8,%9}, {%0,%1,%2,%3};" \
        : "+f"((d)[0]), "+f"((d)[1]), "+f"((d)[2]), "+f"((d)[3]) \
        : "r"((a)[0]), "r"((a)[1]), "r"((a)[2]), "r"((a)[3]), "r"((b)[0]), "r"((b)[1]))

__device__ __forceinline__ uint32_t pack_bf16x2(float lo, float hi) {
    uint32_t r;
    asm("cvt.rn.bf16x2.f32 %0, %1, %2;" : "=r"(r) : "f"(hi), "f"(lo));
    return r;
}
__device__ __forceinline__ float lo_f(uint32_t p) {
    __nv_bfloat162 v = *(__nv_bfloat162*)&p; return __bfloat162float(v.x);
}
__device__ __forceinline__ float hi_f(uint32_t p) {
    __nv_bfloat162 v = *(__nv_bfloat162*)&p; return __bfloat162float(v.y);
}

// ---------------------------------------------------------------------------
// Convert fp32 -> fp16.  sel=0: x (param) -> g_xh16, sel=1: g_o -> g_oh16.
// ---------------------------------------------------------------------------
__global__ void __launch_bounds__(256) convert_h(const float4* __restrict__ xin, int sel)
{
    const int i = blockIdx.x * 256 + threadIdx.x;
    const float4 v = sel ? ((const float4*)g_o)[i] : xin[i];
    __half* dst = sel ? g_oh16 : g_xh16;
    __half2 p0 = __floats2half2_rn(v.x, v.y);
    __half2 p1 = __floats2half2_rn(v.z, v.w);
    uint2 u; u.x = *(uint32_t*)&p0; u.y = *(uint32_t*)&p1;
    ((uint2*)dst)[i] = u;
}

// ---------------------------------------------------------------------------
// Split q/k/v (fp32 [B,S,D]) into bf16 hi/lo pairs for tensor attention.
// ---------------------------------------------------------------------------
__device__ __forceinline__ void split4(float4 v, uint2* hi, uint2* lo, int i)
{
    __nv_bfloat16 h0 = __float2bfloat16(v.x), h1 = __float2bfloat16(v.y);
    __nv_bfloat16 h2 = __float2bfloat16(v.z), h3 = __float2bfloat16(v.w);
    __nv_bfloat162 hp[2] = {{h0, h1}, {h2, h3}};
    __nv_bfloat162 lp[2] = {
        { __float2bfloat16(v.x - __bfloat162float(h0)),
          __float2bfloat16(v.y - __bfloat162float(h1)) },
        { __float2bfloat16(v.z - __bfloat162float(h2)),
          __float2bfloat16(v.w - __bfloat162float(h3)) } };
    hi[i] = *(uint2*)hp;
    lo[i] = *(uint2*)lp;
}

__global__ void __launch_bounds__(256) convert_qkv_split()
{
    const int i = blockIdx.x * 256 + threadIdx.x;
    split4(((const float4*)g_q)[i], (uint2*)g_qh, (uint2*)g_ql, i);
    split4(((const float4*)g_k)[i], (uint2*)g_kh, (uint2*)g_kl, i);
    split4(((const float4*)g_v)[i], (uint2*)g_vh, (uint2*)g_vl, i);
}

// ---------------------------------------------------------------------------
// Transpose + split: W[K,N] fp32 -> Wt[N,K] (hi,lo) fp16. z selects Wq/Wk/Wv/Wo.
// ---------------------------------------------------------------------------
__global__ void __launch_bounds__(256) transpose_split(
    const float* __restrict__ Wq, const float* __restrict__ Wk,
    const float* __restrict__ Wv, const float* __restrict__ Wo)
{
    const float* W = (blockIdx.z == 0) ? Wq : (blockIdx.z == 1) ? Wk
                   : (blockIdx.z == 2) ? Wv : Wo;
    __half* Thi = g_wth[blockIdx.z];
    __half* Tlo = g_wtl[blockIdx.z];

    __shared__ float tile[32][33];
    const int tx = threadIdx.x, ty = threadIdx.y;
    const int k0 = blockIdx.x * 32, n0 = blockIdx.y * 32;

    #pragma unroll
    for (int j = 0; j < 32; j += 8)
        tile[ty + j][tx] = W[(size_t)(k0 + ty + j) * D_ + n0 + tx];
    __syncthreads();
    #pragma unroll
    for (int j = 0; j < 32; j += 8) {
        float v = tile[tx][ty + j];
        __half h = __float2half(v);
        __half l = __float2half(v - __half2float(h));
        const size_t idx = (size_t)(n0 + ty + j) * D_ + k0 + tx;
        Thi[idx] = h;
        Tlo[idx] = l;
    }
}

// ---------------------------------------------------------------------------
// 2-pass split-fp16 GEMM (UNCHANGED from R6)
// ---------------------------------------------------------------------------
#define BK_   32
#define NT_   (D_ / BK_)
#define ROWE_ 40
#define TILE_BYTES (128 * ROWE_ * 2)
#define STAGE_BYTES (3 * TILE_BYTES)
#define GSMEM_BYTES (2 * STAGE_BYTES)

extern __shared__ char dsm[];

__global__ void __launch_bounds__(256, 2) mma_gemm(int mode,
    const float* __restrict__ b0, const float* __restrict__ b1,
    const float* __restrict__ b2, float* __restrict__ dout)
{
    const int z = mode ? 3 : blockIdx.z;
    const __half* A   = mode ? g_oh16 : g_xh16;
    const __half* Bh  = g_wth[z];
    const __half* Bl  = g_wtl[z];
    const float* bias = mode ? b0 : (z == 0 ? b0 : (z == 1 ? b1 : b2));
    float* Out = mode ? dout : (z == 0 ? g_q : (z == 1 ? g_k : g_v));

    const int tid  = threadIdx.x;
    const int lane = tid & 31;
    const int wid  = tid >> 5;
    const int wm   = (wid & 1) * 64;
    const int wn   = (wid >> 1) * 32;
    const int m0 = blockIdx.y * 128;
    const int n0 = blockIdx.x * 128;

    const uint32_t sb = smem_u32(dsm);

    const int cA = tid * 2, cB = tid * 2 + 1;
    const int rA = cA >> 2, qA = cA & 3;
    const int rB = cB >> 2, qB = cB & 3;

    auto issue = [&](int t) {
        const int kc = t * BK_;
        const uint32_t st = sb + (t & 1) * STAGE_BYTES;
        CP_ASYNC16(st + rA * 80 + qA * 16, A  + (size_t)(m0 + rA) * D_ + kc + qA * 8);
        CP_ASYNC16(st + rB * 80 + qB * 16, A  + (size_t)(m0 + rB) * D_ + kc + qB * 8);
        CP_ASYNC16(st + TILE_BYTES   + rA * 80 + qA * 16, Bh + (size_t)(n0 + rA) * D_ + kc + qA * 8);
        CP_ASYNC16(st + TILE_BYTES   + rB * 80 + qB * 16, Bh + (size_t)(n0 + rB) * D_ + kc + qB * 8);
        CP_ASYNC16(st + 2*TILE_BYTES + rA * 80 + qA * 16, Bl + (size_t)(n0 + rA) * D_ + kc + qA * 8);
        CP_ASYNC16(st + 2*TILE_BYTES + rB * 80 + qB * 16, Bl + (size_t)(n0 + rB) * D_ + kc + qB * 8);
        CP_COMMIT();
    };

    float d[4][4][4];
    #pragma unroll
    for (int i = 0; i < 4; ++i)
        #pragma unroll
        for (int j = 0; j < 4; ++j)
            #pragma unroll
            for (int r = 0; r < 4; ++r) d[i][j][r] = 0.f;

    issue(0);

    const int aRow = lane & 15;
    const int aK8  = (lane >> 4) * 8;
    const int bRow = (lane & 7) + ((lane >> 4) & 1) * 8;
    const int bK8  = ((lane >> 3) & 1) * 8;

    for (int t = 0; t < NT_; ++t) {
        if (t + 1 < NT_) { issue(t + 1); CP_WAIT(1); } else { CP_WAIT(0); }
        __syncthreads();

        const uint32_t st = sb + (t & 1) * STAGE_BYTES;
        #pragma unroll
        for (int ks = 0; ks < BK_; ks += 16) {
            uint32_t a[4][4];
            #pragma unroll
            for (int ms = 0; ms < 4; ++ms) {
                uint32_t addr = st + (uint32_t)(wm + ms*16 + aRow) * 80
                              + (uint32_t)(ks + aK8) * 2;
                LDSM_X4(a[ms][0], a[ms][1], a[ms][2], a[ms][3], addr);
            }
            uint32_t bh[4][2], bl[4][2];
            #pragma unroll
            for (int np = 0; np < 2; ++np) {
                uint32_t r0, r1, r2, r3;
                uint32_t boff = (uint32_t)(wn + np*16 + bRow) * 80
                              + (uint32_t)(ks + bK8) * 2;
                LDSM_X4(r0, r1, r2, r3, st + TILE_BYTES + boff);
                bh[np*2+0][0] = r0; bh[np*2+0][1] = r1;
                bh[np*2+1][0] = r2; bh[np*2+1][1] = r3;
                LDSM_X4(r0, r1, r2, r3, st + 2*TILE_BYTES + boff);
                bl[np*2+0][0] = r0; bl[np*2+0][1] = r1;
                bl[np*2+1][0] = r2; bl[np*2+1][1] = r3;
            }
            #pragma unroll
            for (int ms = 0; ms < 4; ++ms)
                #pragma unroll
                for (int ns = 0; ns < 4; ++ns) {
                    MMA_F16(d[ms][ns], a[ms], bh[ns]);
                    MMA_F16(d[ms][ns], a[ms], bl[ns]);
                }
        }
        __syncthreads();
    }

    const int g = lane >> 2, q = lane & 3;
    #pragma unroll
    for (int ns = 0; ns < 4; ++ns) {
        const int col = n0 + wn + ns * 8 + q * 2;
        const float2 bv = *(const float2*)&bias[col];
        #pragma unroll
        for (int ms = 0; ms < 4; ++ms) {
            const int row = m0 + wm + ms * 16 + g;
            float2 v0 = { d[ms][ns][0] + bv.x, d[ms][ns][1] + bv.y };
            float2 v1 = { d[ms][ns][2] + bv.x, d[ms][ns][3] + bv.y };
            *(float2*)&Out[(size_t)row * D_ + col]       = v0;
            *(float2*)&Out[(size_t)(row + 8) * D_ + col] = v1;
        }
    }
}

// ---------------------------------------------------------------------------
// Tensor-core flash attention: pre-split bf16 inputs, cp.async 3-stage pipeline.
// Block: 128 q-rows of one (b,h); 8 warps. kv-tile = 64.
// Stage = {Khi, Klo, Vhi, Vlo} each 64 rows x 72 bf16 (9216 B) = 36864 B; 3 stages.
// ---------------------------------------------------------------------------
#define AROW_ 72
#define ATB_  (64 * AROW_ * 2)        // 9216
#define ASTG_ (4 * ATB_)              // 36864
#define ASMEM_ (3 * ASTG_)            // 110592

__global__ void __launch_bounds__(256, 1) attn_kernel()
{
    const int qb = blockIdx.x;
    const int h  = blockIdx.y;
    const int b  = blockIdx.z;
    const int q0 = qb * 128;
    const size_t hoff = (size_t)h * HD_;

    const int tid  = threadIdx.x;
    const int lane = tid & 31;
    const int wid  = tid >> 5;
    const int g    = lane >> 2;
    const int qd   = lane & 3;

    const uint32_t sb = smem_u32(dsm);

    // staging indices: 2 chunks of 16B per array per thread
    const int c0 = tid * 2, c1 = tid * 2 + 1;
    const int r0c = c0 >> 3, q0c = c0 & 7;
    const int r1c = c1 >> 3, q1c = c1 & 7;

    // ---- Q into stage 0: tiles {Qhi lo-rows, Qhi hi-rows, Qlo lo-rows, Qlo hi-rows}
    {
        const size_t base0 = (size_t)(b*S_ + q0) * D_ + hoff;
        const size_t base1 = (size_t)(b*S_ + q0 + 64) * D_ + hoff;
        CP_ASYNC16(sb + 0*ATB_ + r0c*144 + q0c*16, g_qh + base0 + r0c*D_ + q0c*8);
        CP_ASYNC16(sb + 0*ATB_ + r1c*144 + q1c*16, g_qh + base0 + r1c*D_ + q1c*8);
        CP_ASYNC16(sb + 1*ATB_ + r0c*144 + q0c*16, g_qh + base1 + r0c*D_ + q0c*8);
        CP_ASYNC16(sb + 1*ATB_ + r1c*144 + q1c*16, g_qh + base1 + r1c*D_ + q1c*8);
        CP_ASYNC16(sb + 2*ATB_ + r0c*144 + q0c*16, g_ql + base0 + r0c*D_ + q0c*8);
        CP_ASYNC16(sb + 2*ATB_ + r1c*144 + q1c*16, g_ql + base0 + r1c*D_ + q1c*8);
        CP_ASYNC16(sb + 3*ATB_ + r0c*144 + q0c*16, g_ql + base1 + r0c*D_ + q0c*8);
        CP_ASYNC16(sb + 3*ATB_ + r1c*144 + q1c*16, g_ql + base1 + r1c*D_ + q1c*8);
        CP_COMMIT();
    }

    auto issue_tile = [&](int kt) {
        const int stg = (kt + 1) % 3;
        const uint32_t st = sb + stg * ASTG_;
        const size_t base = (size_t)(b*S_ + kt*64) * D_ + hoff;
        const size_t o0 = base + r0c*D_ + q0c*8;
        const size_t o1 = base + r1c*D_ + q1c*8;
        const uint32_t d0 = r0c*144 + q0c*16;
        const uint32_t d1 = r1c*144 + q1c*16;
        CP_ASYNC16(st + 0*ATB_ + d0, g_kh + o0);
        CP_ASYNC16(st + 0*ATB_ + d1, g_kh + o1);
        CP_ASYNC16(st + 1*ATB_ + d0, g_kl + o0);
        CP_ASYNC16(st + 1*ATB_ + d1, g_kl + o1);
        CP_ASYNC16(st + 2*ATB_ + d0, g_vh + o0);
        CP_ASYNC16(st + 2*ATB_ + d1, g_vh + o1);
        CP_ASYNC16(st + 3*ATB_ + d0, g_vl + o0);
        CP_ASYNC16(st + 3*ATB_ + d1, g_vl + o1);
        CP_COMMIT();
    };

    issue_tile(0);          // -> stage 1
    CP_WAIT(1);             // Q group done
    __syncthreads();

    // ---- Q fragments from stage 0
    uint32_t qhi[4][4], qlo[4][4];
    {
        const uint32_t hbase = sb + ((wid < 4) ? 0 : 1) * ATB_;
        const uint32_t lbase = sb + ((wid < 4) ? 2 : 3) * ATB_;
        const int rr = (wid & 3) * 16 + ((lane >> 3) & 1) * 8 + (lane & 7);
        #pragma unroll
        for (int kat = 0; kat < 4; ++kat) {
            const uint32_t koff = (uint32_t)(kat * 16 + ((lane >> 4) & 1) * 8) * 2;
            LDSM_X4(qhi[kat][0], qhi[kat][1], qhi[kat][2], qhi[kat][3],
                    hbase + (uint32_t)rr * 144 + koff);
            LDSM_X4(qlo[kat][0], qlo[kat][1], qlo[kat][2], qlo[kat][3],
                    lbase + (uint32_t)rr * 144 + koff);
        }
    }

    float o[8][4];
    #pragma unroll
    for (int j = 0; j < 8; ++j)
        #pragma unroll
        for (int r = 0; r < 4; ++r) o[j][r] = 0.f;
    float mrow0 = -1e30f, mrow1 = -1e30f, lrow0 = 0.f, lrow1 = 0.f;

    const int wrow0 = q0 + wid * 16;

    const int kRow = ((lane >> 4) & 1) * 8 + (lane & 7);
    const int kK8  = ((lane >> 3) & 1) * 8;
    const int vRow = ((lane >> 3) & 1) * 8 + (lane & 7);
    const int vC8  = ((lane >> 4) & 1) * 8;

    const int nkt = 2 * (qb + 1);
    for (int kt = 0; kt < nkt; ++kt) {
        const int k0 = kt * 64;
        if (kt + 1 < nkt) { issue_tile(kt + 1); CP_WAIT(1); } else { CP_WAIT(0); }
        __syncthreads();

        const uint32_t st = sb + ((kt + 1) % 3) * ASTG_;
        const uint32_t uKhi = st, uKlo = st + ATB_;
        const uint32_t uVhi = st + 2*ATB_, uVlo = st + 3*ATB_;

        if (k0 <= wrow0 + 15) {
            float s[8][4];
            #pragma unroll
            for (int j = 0; j < 8; ++j)
                #pragma unroll
                for (int r = 0; r < 4; ++r) s[j][r] = 0.f;

            #pragma unroll
            for (int pass = 0; pass < 3; ++pass) {
                const uint32_t Bt = (pass == 1) ? uKlo : uKhi;
                #pragma unroll
                for (int kat = 0; kat < 4; ++kat) {
                    const uint32_t* a = (pass == 2) ? qlo[kat] : qhi[kat];
                    #pragma unroll
                    for (int jp = 0; jp < 4; ++jp) {
                        uint32_t r0, r1, r2, r3;
                        uint32_t addr = Bt + (uint32_t)(jp*16 + kRow) * 144
                                      + (uint32_t)(kat*16 + kK8) * 2;
                        LDSM_X4(r0, r1, r2, r3, addr);
                        uint32_t b0[2] = {r0, r1}, b1[2] = {r2, r3};
                        MMA_BF16(s[jp*2+0], a, b0);
                        MMA_BF16(s[jp*2+1], a, b1);
                    }
                }
            }

            const int row0 = wrow0 + g;
            const int row1 = row0 + 8;
            const bool needmask = (k0 + 63 > wrow0);
            float nm0 = mrow0, nm1 = mrow1;
            #pragma unroll
            for (int j = 0; j < 8; ++j) {
                const int col = k0 + j*8 + qd*2;
                float v0 = s[j][0] * 0.125f, v1 = s[j][1] * 0.125f;
                float v2 = s[j][2] * 0.125f, v3 = s[j][3] * 0.125f;
                if (needmask) {
                    if (col + 0 > row0) v0 = -1e30f;
                    if (col + 1 > row0) v1 = -1e30f;
                    if (col + 0 > row1) v2 = -1e30f;
                    if (col + 1 > row1) v3 = -1e30f;
                }
                s[j][0] = v0; s[j][1] = v1; s[j][2] = v2; s[j][3] = v3;
                nm0 = fmaxf(nm0, fmaxf(v0, v1));
                nm1 = fmaxf(nm1, fmaxf(v2, v3));
            }
            nm0 = fmaxf(nm0, __shfl_xor_sync(0xffffffffu, nm0, 1));
            nm0 = fmaxf(nm0, __shfl_xor_sync(0xffffffffu, nm0, 2));
            nm1 = fmaxf(nm1, __shfl_xor_sync(0xffffffffu, nm1, 1));
            nm1 = fmaxf(nm1, __shfl_xor_sync(0xffffffffu, nm1, 2));

            const float alpha0 = __expf(mrow0 - nm0);
            const float alpha1 = __expf(mrow1 - nm1);
            mrow0 = nm0; mrow1 = nm1;

            uint32_t phi[4][4], plo[4][4];
            float ps0 = 0.f, ps1 = 0.f;
            #pragma unroll
            for (int jp = 0; jp < 4; ++jp) {
                #pragma unroll
                for (int half = 0; half < 2; ++half) {
                    const int j = jp*2 + half;
                    const float p0 = __expf(s[j][0] - nm0);
                    const float p1 = __expf(s[j][1] - nm0);
                    const float p2 = __expf(s[j][2] - nm1);
                    const float p3 = __expf(s[j][3] - nm1);
                    ps0 += p0 + p1; ps1 += p2 + p3;
                    const uint32_t h01 = pack_bf16x2(p0, p1);
                    const uint32_t h23 = pack_bf16x2(p2, p3);
                    phi[jp][0 + half*2] = h01;
                    phi[jp][1 + half*2] = h23;
                    plo[jp][0 + half*2] = pack_bf16x2(p0 - lo_f(h01), p1 - hi_f(h01));
                    plo[jp][1 + half*2] = pack_bf16x2(p2 - lo_f(h23), p3 - hi_f(h23));
                }
            }
            ps0 += __shfl_xor_sync(0xffffffffu, ps0, 1);
            ps0 += __shfl_xor_sync(0xffffffffu, ps0, 2);
            ps1 += __shfl_xor_sync(0xffffffffu, ps1, 1);
            ps1 += __shfl_xor_sync(0xffffffffu, ps1, 2);
            lrow0 = lrow0 * alpha0 + ps0;
            lrow1 = lrow1 * alpha1 + ps1;
            #pragma unroll
            for (int j = 0; j < 8; ++j) {
                o[j][0] *= alpha0; o[j][1] *= alpha0;
                o[j][2] *= alpha1; o[j][3] *= alpha1;
            }

            #pragma unroll
            for (int pass = 0; pass < 3; ++pass) {
                const uint32_t Bt = (pass == 1) ? uVlo : uVhi;
                #pragma unroll
                for (int kat = 0; kat < 4; ++kat) {
                    const uint32_t* a = (pass == 2) ? plo[kat] : phi[kat];
                    #pragma unroll
                    for (int jp = 0; jp < 4; ++jp) {
                        uint32_t r0, r1, r2, r3;
                        uint32_t addr = Bt + (uint32_t)(kat*16 + vRow) * 144
                                      + (uint32_t)(jp*16 + vC8) * 2;
                        LDSM_X4T(r0, r1, r2, r3, addr);
                        uint32_t b0[2] = {r0, r1}, b1[2] = {r2, r3};
                        MMA_BF16(o[jp*2+0], a, b0);
                        MMA_BF16(o[jp*2+1], a, b1);
                    }
                }
            }
        }
    }

    const float inv0 = 1.f / lrow0;
    const float inv1 = 1.f / lrow1;
    const int row0 = q0 + wid*16 + g;
    #pragma unroll
    for (int j = 0; j < 8; ++j) {
        const int col = j*8 + qd*2;
        float2 v0 = { o[j][0] * inv0, o[j][1] * inv0 };
        float2 v1 = { o[j][2] * inv1, o[j][3] * inv1 };
        *(float2*)&g_o[(size_t)(b*S_ + row0) * D_ + hoff + col]     = v0;
        *(float2*)&g_o[(size_t)(b*S_ + row0 + 8) * D_ + hoff + col] = v1;
    }
}

// ---------------------------------------------------------------------------
extern "C" void kernel_launch(void* const* d_in, const int* in_sizes, int n_in,
                              void* d_out, int out_size)
{
    (void)in_sizes; (void)n_in; (void)out_size;
    const float* x  = (const float*)d_in[0];
    const float* Wq = (const float*)d_in[1];
    const float* bq = (const float*)d_in[2];
    const float* Wk = (const float*)d_in[3];
    const float* bk = (const float*)d_in[4];
    const float* Wv = (const float*)d_in[5];
    const float* bv = (const float*)d_in[6];
    const float* Wo = (const float*)d_in[7];
    const float* bo = (const float*)d_in[8];
    float* out = (float*)d_out;

    cudaFuncSetAttribute(mma_gemm, cudaFuncAttributeMaxDynamicSharedMemorySize, GSMEM_BYTES);
    cudaFuncSetAttribute(attn_kernel, cudaFuncAttributeMaxDynamicSharedMemorySize, ASMEM_);

    convert_h<<<(M_*D_/4 + 255)/256, 256>>>((const float4*)x, 0);
    dim3 tg(D_/32, D_/32, 4);
    transpose_split<<<tg, dim3(32, 8)>>>(Wq, Wk, Wv, Wo);

    dim3 gq(D_/128, M_/128, 3);
    mma_gemm<<<gq, 256, GSMEM_BYTES>>>(0, bq, bk, bv, nullptr);

    convert_qkv_split<<<(M_*D_/4 + 255)/256, 256>>>();

    dim3 ga(S_/128, H_, B_);
    attn_kernel<<<ga, 256, ASMEM_>>>();

    convert_h<<<(M_*D_/4 + 255)/256, 256>>>(nullptr, 1);
    dim3 go(D_/128, M_/128, 1);
    mma_gemm<<<go, 256, GSMEM_BYTES>>>(1, bo, nullptr, nullptr, out);
}

// round 8
// speedup vs baseline: 6.9171x; 1.0701x over previous
#include <cuda_runtime.h>
#include <cuda_bf16.h>
#include <cuda_fp16.h>
#include <cstdint>

#define B_  2
#define S_  2048
#define D_  1024
#define H_  16
#define HD_ 64
#define M_  (B_*S_)   // 4096

// ---------------------------------------------------------------------------
// Scratch (allocation-free rule: static device globals)
// ---------------------------------------------------------------------------
__device__ __half g_xh16[M_*D_];              // fp16(x)
__device__ __half g_oh16[M_*D_];              // fp16(attention out)
__device__ __half g_wth[4][D_*D_], g_wtl[4][D_*D_];  // W^T split fp16 [N,K]

// split-bf16 q/k/v for tensor attention (written by QKV GEMM epilogue)
__device__ __nv_bfloat16 g_qh[M_*D_], g_ql[M_*D_];
__device__ __nv_bfloat16 g_kh[M_*D_], g_kl[M_*D_];
__device__ __nv_bfloat16 g_vh[M_*D_], g_vl[M_*D_];

// ---------------------------------------------------------------------------
__device__ __forceinline__ uint32_t smem_u32(const void* p) {
    uint32_t a;
    asm("{ .reg .u64 t; cvta.to.shared.u64 t, %1; cvt.u32.u64 %0, t; }" : "=r"(a) : "l"(p));
    return a;
}

#define CP_ASYNC16(dst, src) \
    asm volatile("cp.async.cg.shared.global [%0], [%1], 16;" :: "r"(dst), "l"(src))
#define CP_COMMIT()  asm volatile("cp.async.commit_group;" ::: "memory")
#define CP_WAIT(n)   asm volatile("cp.async.wait_group %0;" :: "n"(n) : "memory")

#define LDSM_X4(r0, r1, r2, r3, addr) \
    asm volatile("ldmatrix.sync.aligned.m8n8.x4.shared.b16 {%0,%1,%2,%3}, [%4];" \
        : "=r"(r0), "=r"(r1), "=r"(r2), "=r"(r3) : "r"(addr))

#define LDSM_X4T(r0, r1, r2, r3, addr) \
    asm volatile("ldmatrix.sync.aligned.m8n8.x4.trans.shared.b16 {%0,%1,%2,%3}, [%4];" \
        : "=r"(r0), "=r"(r1), "=r"(r2), "=r"(r3) : "r"(addr))

#define MMA_BF16(d, a, b) \
    asm volatile("mma.sync.aligned.m16n8k16.row.col.f32.bf16.bf16.f32 " \
        "{%0,%1,%2,%3}, {%4,%5,%6,%7}, {%8,%9}, {%0,%1,%2,%3};" \
        : "+f"((d)[0]), "+f"((d)[1]), "+f"((d)[2]), "+f"((d)[3]) \
        : "r"((a)[0]), "r"((a)[1]), "r"((a)[2]), "r"((a)[3]), "r"((b)[0]), "r"((b)[1]))

#define MMA_F16(d, a, b) \
    asm volatile("mma.sync.aligned.m16n8k16.row.col.f32.f16.f16.f32 " \
        "{%0,%1,%2,%3}, {%4,%5,%6,%7}, {%8,%9}, {%0,%1,%2,%3};" \
        : "+f"((d)[0]), "+f"((d)[1]), "+f"((d)[2]), "+f"((d)[3]) \
        : "r"((a)[0]), "r"((a)[1]), "r"((a)[2]), "r"((a)[3]), "r"((b)[0]), "r"((b)[1]))

__device__ __forceinline__ uint32_t pack_bf16x2(float lo, float hi) {
    uint32_t r;
    asm("cvt.rn.bf16x2.f32 %0, %1, %2;" : "=r"(r) : "f"(hi), "f"(lo));
    return r;
}
__device__ __forceinline__ float lo_f(uint32_t p) {
    __nv_bfloat162 v = *(__nv_bfloat162*)&p; return __bfloat162float(v.x);
}
__device__ __forceinline__ float hi_f(uint32_t p) {
    __nv_bfloat162 v = *(__nv_bfloat162*)&p; return __bfloat162float(v.y);
}

// split two fp32 into (hi bf16x2, lo bf16x2)
__device__ __forceinline__ void split2(float x, float y, uint32_t& hi, uint32_t& lo) {
    hi = pack_bf16x2(x, y);
    lo = pack_bf16x2(x - lo_f(hi), y - hi_f(hi));
}

// ---------------------------------------------------------------------------
// Convert fp32 x -> fp16 g_xh16.
// ---------------------------------------------------------------------------
__global__ void __launch_bounds__(256) convert_h(const float4* __restrict__ xin)
{
    const int i = blockIdx.x * 256 + threadIdx.x;
    const float4 v = xin[i];
    __half2 p0 = __floats2half2_rn(v.x, v.y);
    __half2 p1 = __floats2half2_rn(v.z, v.w);
    uint2 u; u.x = *(uint32_t*)&p0; u.y = *(uint32_t*)&p1;
    ((uint2*)g_xh16)[i] = u;
}

// ---------------------------------------------------------------------------
// Transpose + split: W[K,N] fp32 -> Wt[N,K] (hi,lo) fp16. z selects Wq/Wk/Wv/Wo.
// ---------------------------------------------------------------------------
__global__ void __launch_bounds__(256) transpose_split(
    const float* __restrict__ Wq, const float* __restrict__ Wk,
    const float* __restrict__ Wv, const float* __restrict__ Wo)
{
    const float* W = (blockIdx.z == 0) ? Wq : (blockIdx.z == 1) ? Wk
                   : (blockIdx.z == 2) ? Wv : Wo;
    __half* Thi = g_wth[blockIdx.z];
    __half* Tlo = g_wtl[blockIdx.z];

    __shared__ float tile[32][33];
    const int tx = threadIdx.x, ty = threadIdx.y;
    const int k0 = blockIdx.x * 32, n0 = blockIdx.y * 32;

    #pragma unroll
    for (int j = 0; j < 32; j += 8)
        tile[ty + j][tx] = W[(size_t)(k0 + ty + j) * D_ + n0 + tx];
    __syncthreads();
    #pragma unroll
    for (int j = 0; j < 32; j += 8) {
        float v = tile[tx][ty + j];
        __half h = __float2half(v);
        __half l = __float2half(v - __half2float(h));
        const size_t idx = (size_t)(n0 + ty + j) * D_ + k0 + tx;
        Thi[idx] = h;
        Tlo[idx] = l;
    }
}

// ---------------------------------------------------------------------------
// 2-pass split-fp16 GEMM. mode 0: QKV (z selects), epilogue writes split-bf16
// q/k/v directly. mode 1: out projection -> dout fp32.
// ---------------------------------------------------------------------------
#define BK_   32
#define NT_   (D_ / BK_)
#define ROWE_ 40
#define TILE_BYTES (128 * ROWE_ * 2)
#define STAGE_BYTES (3 * TILE_BYTES)
#define GSMEM_BYTES (2 * STAGE_BYTES)

extern __shared__ char dsm[];

__global__ void __launch_bounds__(256, 2) mma_gemm(int mode,
    const float* __restrict__ b0, const float* __restrict__ b1,
    const float* __restrict__ b2, float* __restrict__ dout)
{
    const int z = mode ? 3 : blockIdx.z;
    const __half* A   = mode ? g_oh16 : g_xh16;
    const __half* Bh  = g_wth[z];
    const __half* Bl  = g_wtl[z];
    const float* bias = mode ? b0 : (z == 0 ? b0 : (z == 1 ? b1 : b2));

    const int tid  = threadIdx.x;
    const int lane = tid & 31;
    const int wid  = tid >> 5;
    const int wm   = (wid & 1) * 64;
    const int wn   = (wid >> 1) * 32;
    const int m0 = blockIdx.y * 128;
    const int n0 = blockIdx.x * 128;

    const uint32_t sb = smem_u32(dsm);

    const int cA = tid * 2, cB = tid * 2 + 1;
    const int rA = cA >> 2, qA = cA & 3;
    const int rB = cB >> 2, qB = cB & 3;

    auto issue = [&](int t) {
        const int kc = t * BK_;
        const uint32_t st = sb + (t & 1) * STAGE_BYTES;
        CP_ASYNC16(st + rA * 80 + qA * 16, A  + (size_t)(m0 + rA) * D_ + kc + qA * 8);
        CP_ASYNC16(st + rB * 80 + qB * 16, A  + (size_t)(m0 + rB) * D_ + kc + qB * 8);
        CP_ASYNC16(st + TILE_BYTES   + rA * 80 + qA * 16, Bh + (size_t)(n0 + rA) * D_ + kc + qA * 8);
        CP_ASYNC16(st + TILE_BYTES   + rB * 80 + qB * 16, Bh + (size_t)(n0 + rB) * D_ + kc + qB * 8);
        CP_ASYNC16(st + 2*TILE_BYTES + rA * 80 + qA * 16, Bl + (size_t)(n0 + rA) * D_ + kc + qA * 8);
        CP_ASYNC16(st + 2*TILE_BYTES + rB * 80 + qB * 16, Bl + (size_t)(n0 + rB) * D_ + kc + qB * 8);
        CP_COMMIT();
    };

    float d[4][4][4];
    #pragma unroll
    for (int i = 0; i < 4; ++i)
        #pragma unroll
        for (int j = 0; j < 4; ++j)
            #pragma unroll
            for (int r = 0; r < 4; ++r) d[i][j][r] = 0.f;

    issue(0);

    const int aRow = lane & 15;
    const int aK8  = (lane >> 4) * 8;
    const int bRow = (lane & 7) + ((lane >> 4) & 1) * 8;
    const int bK8  = ((lane >> 3) & 1) * 8;

    for (int t = 0; t < NT_; ++t) {
        if (t + 1 < NT_) { issue(t + 1); CP_WAIT(1); } else { CP_WAIT(0); }
        __syncthreads();

        const uint32_t st = sb + (t & 1) * STAGE_BYTES;
        #pragma unroll
        for (int ks = 0; ks < BK_; ks += 16) {
            uint32_t a[4][4];
            #pragma unroll
            for (int ms = 0; ms < 4; ++ms) {
                uint32_t addr = st + (uint32_t)(wm + ms*16 + aRow) * 80
                              + (uint32_t)(ks + aK8) * 2;
                LDSM_X4(a[ms][0], a[ms][1], a[ms][2], a[ms][3], addr);
            }
            uint32_t bh[4][2], bl[4][2];
            #pragma unroll
            for (int np = 0; np < 2; ++np) {
                uint32_t r0, r1, r2, r3;
                uint32_t boff = (uint32_t)(wn + np*16 + bRow) * 80
                              + (uint32_t)(ks + bK8) * 2;
                LDSM_X4(r0, r1, r2, r3, st + TILE_BYTES + boff);
                bh[np*2+0][0] = r0; bh[np*2+0][1] = r1;
                bh[np*2+1][0] = r2; bh[np*2+1][1] = r3;
                LDSM_X4(r0, r1, r2, r3, st + 2*TILE_BYTES + boff);
                bl[np*2+0][0] = r0; bl[np*2+0][1] = r1;
                bl[np*2+1][0] = r2; bl[np*2+1][1] = r3;
            }
            #pragma unroll
            for (int ms = 0; ms < 4; ++ms)
                #pragma unroll
                for (int ns = 0; ns < 4; ++ns) {
                    MMA_F16(d[ms][ns], a[ms], bh[ns]);
                    MMA_F16(d[ms][ns], a[ms], bl[ns]);
                }
        }
        __syncthreads();
    }

    const int g = lane >> 2, q = lane & 3;
    if (mode == 0) {
        __nv_bfloat16* Hi = (z == 0) ? g_qh : (z == 1) ? g_kh : g_vh;
        __nv_bfloat16* Lo = (z == 0) ? g_ql : (z == 1) ? g_kl : g_vl;
        #pragma unroll
        for (int ns = 0; ns < 4; ++ns) {
            const int col = n0 + wn + ns * 8 + q * 2;
            const float2 bv = *(const float2*)&bias[col];
            #pragma unroll
            for (int ms = 0; ms < 4; ++ms) {
                const int row = m0 + wm + ms * 16 + g;
                uint32_t h0, l0, h1, l1;
                split2(d[ms][ns][0] + bv.x, d[ms][ns][1] + bv.y, h0, l0);
                split2(d[ms][ns][2] + bv.x, d[ms][ns][3] + bv.y, h1, l1);
                *(uint32_t*)&Hi[(size_t)row * D_ + col]       = h0;
                *(uint32_t*)&Lo[(size_t)row * D_ + col]       = l0;
                *(uint32_t*)&Hi[(size_t)(row + 8) * D_ + col] = h1;
                *(uint32_t*)&Lo[(size_t)(row + 8) * D_ + col] = l1;
            }
        }
    } else {
        #pragma unroll
        for (int ns = 0; ns < 4; ++ns) {
            const int col = n0 + wn + ns * 8 + q * 2;
            const float2 bv = *(const float2*)&bias[col];
            #pragma unroll
            for (int ms = 0; ms < 4; ++ms) {
                const int row = m0 + wm + ms * 16 + g;
                float2 v0 = { d[ms][ns][0] + bv.x, d[ms][ns][1] + bv.y };
                float2 v1 = { d[ms][ns][2] + bv.x, d[ms][ns][3] + bv.y };
                *(float2*)&dout[(size_t)row * D_ + col]       = v0;
                *(float2*)&dout[(size_t)(row + 8) * D_ + col] = v1;
            }
        }
    }
}

// ---------------------------------------------------------------------------
// Tensor-core flash attention: pre-split bf16 inputs, cp.async 3-stage pipe.
// B-fragments (K/V) loaded ONCE and reused across hi/lo passes.
// Epilogue writes fp16 g_oh16 directly.
// ---------------------------------------------------------------------------
#define AROW_ 72
#define ATB_  (64 * AROW_ * 2)        // 9216
#define ASTG_ (4 * ATB_)              // 36864
#define ASMEM_ (3 * ASTG_)            // 110592

__global__ void __launch_bounds__(256, 1) attn_kernel()
{
    const int qb = blockIdx.x;
    const int h  = blockIdx.y;
    const int b  = blockIdx.z;
    const int q0 = qb * 128;
    const size_t hoff = (size_t)h * HD_;

    const int tid  = threadIdx.x;
    const int lane = tid & 31;
    const int wid  = tid >> 5;
    const int g    = lane >> 2;
    const int qd   = lane & 3;

    const uint32_t sb = smem_u32(dsm);

    const int c0 = tid * 2, c1 = tid * 2 + 1;
    const int r0c = c0 >> 3, q0c = c0 & 7;
    const int r1c = c1 >> 3, q1c = c1 & 7;

    // ---- Q into stage 0
    {
        const size_t base0 = (size_t)(b*S_ + q0) * D_ + hoff;
        const size_t base1 = (size_t)(b*S_ + q0 + 64) * D_ + hoff;
        CP_ASYNC16(sb + 0*ATB_ + r0c*144 + q0c*16, g_qh + base0 + r0c*D_ + q0c*8);
        CP_ASYNC16(sb + 0*ATB_ + r1c*144 + q1c*16, g_qh + base0 + r1c*D_ + q1c*8);
        CP_ASYNC16(sb + 1*ATB_ + r0c*144 + q0c*16, g_qh + base1 + r0c*D_ + q0c*8);
        CP_ASYNC16(sb + 1*ATB_ + r1c*144 + q1c*16, g_qh + base1 + r1c*D_ + q1c*8);
        CP_ASYNC16(sb + 2*ATB_ + r0c*144 + q0c*16, g_ql + base0 + r0c*D_ + q0c*8);
        CP_ASYNC16(sb + 2*ATB_ + r1c*144 + q1c*16, g_ql + base0 + r1c*D_ + q1c*8);
        CP_ASYNC16(sb + 3*ATB_ + r0c*144 + q0c*16, g_ql + base1 + r0c*D_ + q0c*8);
        CP_ASYNC16(sb + 3*ATB_ + r1c*144 + q1c*16, g_ql + base1 + r1c*D_ + q1c*8);
        CP_COMMIT();
    }

    auto issue_tile = [&](int kt) {
        const int stg = (kt + 1) % 3;
        const uint32_t st = sb + stg * ASTG_;
        const size_t base = (size_t)(b*S_ + kt*64) * D_ + hoff;
        const size_t o0 = base + r0c*D_ + q0c*8;
        const size_t o1 = base + r1c*D_ + q1c*8;
        const uint32_t d0 = r0c*144 + q0c*16;
        const uint32_t d1 = r1c*144 + q1c*16;
        CP_ASYNC16(st + 0*ATB_ + d0, g_kh + o0);
        CP_ASYNC16(st + 0*ATB_ + d1, g_kh + o1);
        CP_ASYNC16(st + 1*ATB_ + d0, g_kl + o0);
        CP_ASYNC16(st + 1*ATB_ + d1, g_kl + o1);
        CP_ASYNC16(st + 2*ATB_ + d0, g_vh + o0);
        CP_ASYNC16(st + 2*ATB_ + d1, g_vh + o1);
        CP_ASYNC16(st + 3*ATB_ + d0, g_vl + o0);
        CP_ASYNC16(st + 3*ATB_ + d1, g_vl + o1);
        CP_COMMIT();
    };

    issue_tile(0);
    CP_WAIT(1);
    __syncthreads();

    // ---- Q fragments from stage 0
    uint32_t qhi[4][4], qlo[4][4];
    {
        const uint32_t hbase = sb + ((wid < 4) ? 0 : 1) * ATB_;
        const uint32_t lbase = sb + ((wid < 4) ? 2 : 3) * ATB_;
        const int rr = (wid & 3) * 16 + ((lane >> 3) & 1) * 8 + (lane & 7);
        #pragma unroll
        for (int kat = 0; kat < 4; ++kat) {
            const uint32_t koff = (uint32_t)(kat * 16 + ((lane >> 4) & 1) * 8) * 2;
            LDSM_X4(qhi[kat][0], qhi[kat][1], qhi[kat][2], qhi[kat][3],
                    hbase + (uint32_t)rr * 144 + koff);
            LDSM_X4(qlo[kat][0], qlo[kat][1], qlo[kat][2], qlo[kat][3],
                    lbase + (uint32_t)rr * 144 + koff);
        }
    }

    float o[8][4];
    #pragma unroll
    for (int j = 0; j < 8; ++j)
        #pragma unroll
        for (int r = 0; r < 4; ++r) o[j][r] = 0.f;
    float mrow0 = -1e30f, mrow1 = -1e30f, lrow0 = 0.f, lrow1 = 0.f;

    const int wrow0 = q0 + wid * 16;

    const int kRow = ((lane >> 4) & 1) * 8 + (lane & 7);
    const int kK8  = ((lane >> 3) & 1) * 8;
    const int vRow = ((lane >> 3) & 1) * 8 + (lane & 7);
    const int vC8  = ((lane >> 4) & 1) * 8;

    const int nkt = 2 * (qb + 1);
    for (int kt = 0; kt < nkt; ++kt) {
        const int k0 = kt * 64;
        if (kt + 1 < nkt) { issue_tile(kt + 1); CP_WAIT(1); } else { CP_WAIT(0); }
        __syncthreads();

        const uint32_t st = sb + ((kt + 1) % 3) * ASTG_;
        const uint32_t uKhi = st, uKlo = st + ATB_;
        const uint32_t uVhi = st + 2*ATB_, uVlo = st + 3*ATB_;

        if (k0 <= wrow0 + 15) {
            // ---- S = Qh*Kh + Ql*Kh + Qh*Kl; Kh frags loaded once
            float s[8][4];
            #pragma unroll
            for (int j = 0; j < 8; ++j)
                #pragma unroll
                for (int r = 0; r < 4; ++r) s[j][r] = 0.f;

            #pragma unroll
            for (int kat = 0; kat < 4; ++kat) {
                #pragma unroll
                for (int jp = 0; jp < 4; ++jp) {
                    const uint32_t roff = (uint32_t)(jp*16 + kRow) * 144
                                        + (uint32_t)(kat*16 + kK8) * 2;
                    uint32_t r0, r1, r2, r3;
                    LDSM_X4(r0, r1, r2, r3, uKhi + roff);
                    uint32_t b0[2] = {r0, r1}, b1[2] = {r2, r3};
                    MMA_BF16(s[jp*2+0], qhi[kat], b0);
                    MMA_BF16(s[jp*2+1], qhi[kat], b1);
                    MMA_BF16(s[jp*2+0], qlo[kat], b0);
                    MMA_BF16(s[jp*2+1], qlo[kat], b1);
                    LDSM_X4(r0, r1, r2, r3, uKlo + roff);
                    uint32_t c0f[2] = {r0, r1}, c1f[2] = {r2, r3};
                    MMA_BF16(s[jp*2+0], qhi[kat], c0f);
                    MMA_BF16(s[jp*2+1], qhi[kat], c1f);
                }
            }

            // ---- online softmax
            const int row0 = wrow0 + g;
            const int row1 = row0 + 8;
            const bool needmask = (k0 + 63 > wrow0);
            float nm0 = mrow0, nm1 = mrow1;
            #pragma unroll
            for (int j = 0; j < 8; ++j) {
                const int col = k0 + j*8 + qd*2;
                float v0 = s[j][0] * 0.125f, v1 = s[j][1] * 0.125f;
                float v2 = s[j][2] * 0.125f, v3 = s[j][3] * 0.125f;
                if (needmask) {
                    if (col + 0 > row0) v0 = -1e30f;
                    if (col + 1 > row0) v1 = -1e30f;
                    if (col + 0 > row1) v2 = -1e30f;
                    if (col + 1 > row1) v3 = -1e30f;
                }
                s[j][0] = v0; s[j][1] = v1; s[j][2] = v2; s[j][3] = v3;
                nm0 = fmaxf(nm0, fmaxf(v0, v1));
                nm1 = fmaxf(nm1, fmaxf(v2, v3));
            }
            nm0 = fmaxf(nm0, __shfl_xor_sync(0xffffffffu, nm0, 1));
            nm0 = fmaxf(nm0, __shfl_xor_sync(0xffffffffu, nm0, 2));
            nm1 = fmaxf(nm1, __shfl_xor_sync(0xffffffffu, nm1, 1));
            nm1 = fmaxf(nm1, __shfl_xor_sync(0xffffffffu, nm1, 2));

            const float alpha0 = __expf(mrow0 - nm0);
            const float alpha1 = __expf(mrow1 - nm1);
            mrow0 = nm0; mrow1 = nm1;

            uint32_t phi[4][4], plo[4][4];
            float ps0 = 0.f, ps1 = 0.f;
            #pragma unroll
            for (int jp = 0; jp < 4; ++jp) {
                #pragma unroll
                for (int half = 0; half < 2; ++half) {
                    const int j = jp*2 + half;
                    const float p0 = __expf(s[j][0] - nm0);
                    const float p1 = __expf(s[j][1] - nm0);
                    const float p2 = __expf(s[j][2] - nm1);
                    const float p3 = __expf(s[j][3] - nm1);
                    ps0 += p0 + p1; ps1 += p2 + p3;
                    const uint32_t h01 = pack_bf16x2(p0, p1);
                    const uint32_t h23 = pack_bf16x2(p2, p3);
                    phi[jp][0 + half*2] = h01;
                    phi[jp][1 + half*2] = h23;
                    plo[jp][0 + half*2] = pack_bf16x2(p0 - lo_f(h01), p1 - hi_f(h01));
                    plo[jp][1 + half*2] = pack_bf16x2(p2 - lo_f(h23), p3 - hi_f(h23));
                }
            }
            ps0 += __shfl_xor_sync(0xffffffffu, ps0, 1);
            ps0 += __shfl_xor_sync(0xffffffffu, ps0, 2);
            ps1 += __shfl_xor_sync(0xffffffffu, ps1, 1);
            ps1 += __shfl_xor_sync(0xffffffffu, ps1, 2);
            lrow0 = lrow0 * alpha0 + ps0;
            lrow1 = lrow1 * alpha1 + ps1;
            #pragma unroll
            for (int j = 0; j < 8; ++j) {
                o[j][0] *= alpha0; o[j][1] *= alpha0;
                o[j][2] *= alpha1; o[j][3] *= alpha1;
            }

            // ---- O += Ph*Vh + Pl*Vh + Ph*Vl; Vh frags loaded once
            #pragma unroll
            for (int kat = 0; kat < 4; ++kat) {
                #pragma unroll
                for (int jp = 0; jp < 4; ++jp) {
                    const uint32_t roff = (uint32_t)(kat*16 + vRow) * 144
                                        + (uint32_t)(jp*16 + vC8) * 2;
                    uint32_t r0, r1, r2, r3;
                    LDSM_X4T(r0, r1, r2, r3, uVhi + roff);
                    uint32_t b0[2] = {r0, r1}, b1[2] = {r2, r3};
                    MMA_BF16(o[jp*2+0], phi[kat], b0);
                    MMA_BF16(o[jp*2+1], phi[kat], b1);
                    MMA_BF16(o[jp*2+0], plo[kat], b0);
                    MMA_BF16(o[jp*2+1], plo[kat], b1);
                    LDSM_X4T(r0, r1, r2, r3, uVlo + roff);
                    uint32_t c0f[2] = {r0, r1}, c1f[2] = {r2, r3};
                    MMA_BF16(o[jp*2+0], phi[kat], c0f);
                    MMA_BF16(o[jp*2+1], phi[kat], c1f);
                }
            }
        }
    }

    // ---- normalize + write fp16 [B,S,D] directly
    const float inv0 = 1.f / lrow0;
    const float inv1 = 1.f / lrow1;
    const int row0 = q0 + wid*16 + g;
    #pragma unroll
    for (int j = 0; j < 8; ++j) {
        const int col = j*8 + qd*2;
        __half2 v0 = __floats2half2_rn(o[j][0] * inv0, o[j][1] * inv0);
        __half2 v1 = __floats2half2_rn(o[j][2] * inv1, o[j][3] * inv1);
        *(uint32_t*)&g_oh16[(size_t)(b*S_ + row0) * D_ + hoff + col]     = *(uint32_t*)&v0;
        *(uint32_t*)&g_oh16[(size_t)(b*S_ + row0 + 8) * D_ + hoff + col] = *(uint32_t*)&v1;
    }
}

// ---------------------------------------------------------------------------
extern "C" void kernel_launch(void* const* d_in, const int* in_sizes, int n_in,
                              void* d_out, int out_size)
{
    (void)in_sizes; (void)n_in; (void)out_size;
    const float* x  = (const float*)d_in[0];
    const float* Wq = (const float*)d_in[1];
    const float* bq = (const float*)d_in[2];
    const float* Wk = (const float*)d_in[3];
    const float* bk = (const float*)d_in[4];
    const float* Wv = (const float*)d_in[5];
    const float* bv = (const float*)d_in[6];
    const float* Wo = (const float*)d_in[7];
    const float* bo = (const float*)d_in[8];
    float* out = (float*)d_out;

    cudaFuncSetAttribute(mma_gemm, cudaFuncAttributeMaxDynamicSharedMemorySize, GSMEM_BYTES);
    cudaFuncSetAttribute(attn_kernel, cudaFuncAttributeMaxDynamicSharedMemorySize, ASMEM_);

    convert_h<<<(M_*D_/4 + 255)/256, 256>>>((const float4*)x);
    dim3 tg(D_/32, D_/32, 4);
    transpose_split<<<tg, dim3(32, 8)>>>(Wq, Wk, Wv, Wo);

    dim3 gq(D_/128, M_/128, 3);
    mma_gemm<<<gq, 256, GSMEM_BYTES>>>(0, bq, bk, bv, nullptr);

    dim3 ga(S_/128, H_, B_);
    attn_kernel<<<ga, 256, ASMEM_>>>();

    dim3 go(D_/128, M_/128, 1);
    mma_gemm<<<go, 256, GSMEM_BYTES>>>(1, bo, nullptr, nullptr, out);
}